// round 10
// baseline (speedup 1.0000x reference)
#include <cuda_runtime.h>
#include <cuda_bf16.h>
#include <math.h>
#include <stdint.h>

// Problem constants
#define Bsz 4
#define Tn 2048
#define Cn 2048
#define Hn 16
#define DKn 64
#define DVn 128
#define Mtok (Bsz*Tn)          // 8192
#define KEYD (Hn*DKn)          // 1024
#define VALD (Hn*DVn)          // 2048

// -------------------- scratch (device globals, no allocation) --------------------
__device__ float g_qk[(size_t)Mtok*2048];   // x @ qk_w^T
__device__ float g_vg[(size_t)Mtok*4096];   // x @ vg_w^T
__device__ float g_q [(size_t)Mtok*KEYD];
__device__ float g_k [(size_t)Mtok*KEYD];
__device__ float g_v [(size_t)Mtok*VALD];
__device__ float g_dc[(size_t)Mtok*Hn];
__device__ float g_bt[(size_t)Mtok*Hn];
__device__ float g_op[(size_t)Mtok*VALD];
__device__ float g_wt[(size_t)Cn*32];       // transposed [a_w;b_w]

// bf16 hi/lo split operands for the tensor GEMMs
__device__ __nv_bfloat16 g_xh [(size_t)Mtok*Cn],  g_xl [(size_t)Mtok*Cn];
__device__ __nv_bfloat16 g_qwh[(size_t)2048*Cn],  g_qwl[(size_t)2048*Cn];
__device__ __nv_bfloat16 g_vwh[(size_t)4096*Cn],  g_vwl[(size_t)4096*Cn];
__device__ __nv_bfloat16 g_owh[(size_t)2048*Cn],  g_owl[(size_t)2048*Cn];
__device__ __nv_bfloat16 g_obh[(size_t)Mtok*VALD], g_obl[(size_t)Mtok*VALD];

// -------------------- cp.async helpers --------------------
__device__ __forceinline__ void cp16(void* s, const void* g) {
    unsigned ss = (unsigned)__cvta_generic_to_shared(s);
    asm volatile("cp.async.cg.shared.global [%0], [%1], 16;\n" :: "r"(ss), "l"(g));
}
__device__ __forceinline__ void cp16s(unsigned saddr, const void* g) {
    asm volatile("cp.async.cg.shared.global [%0], [%1], 16;\n" :: "r"(saddr), "l"(g));
}
__device__ __forceinline__ void cp4(void* s, const void* g) {
    unsigned ss = (unsigned)__cvta_generic_to_shared(s);
    asm volatile("cp.async.ca.shared.global [%0], [%1], 4;\n" :: "r"(ss), "l"(g));
}
#define CP_COMMIT asm volatile("cp.async.commit_group;\n" ::: "memory")
#define CP_WAIT2  asm volatile("cp.async.wait_group 2;\n" ::: "memory")
#define CP_WAIT1  asm volatile("cp.async.wait_group 1;\n" ::: "memory")
#define CP_WAIT0  asm volatile("cp.async.wait_group 0;\n" ::: "memory")

// bf16 mma m16n8k16
__device__ __forceinline__ void mma16(float* c, const unsigned* a, const unsigned* b) {
    asm volatile(
        "mma.sync.aligned.m16n8k16.row.col.f32.bf16.bf16.f32 "
        "{%0,%1,%2,%3},{%4,%5,%6,%7},{%8,%9},{%0,%1,%2,%3};\n"
        : "+f"(c[0]), "+f"(c[1]), "+f"(c[2]), "+f"(c[3])
        : "r"(a[0]), "r"(a[1]), "r"(a[2]), "r"(a[3]), "r"(b[0]), "r"(b[1]));
}

__device__ __forceinline__ void ldm_x4(unsigned& r0, unsigned& r1,
                                       unsigned& r2, unsigned& r3, unsigned addr) {
    asm volatile("ldmatrix.sync.aligned.m8n8.x4.shared.b16 {%0,%1,%2,%3}, [%4];"
                 : "=r"(r0), "=r"(r1), "=r"(r2), "=r"(r3) : "r"(addr));
}

// ==================== bf16 hi/lo split ====================
__global__ __launch_bounds__(256) void split_bf16(
    const float* __restrict__ in, __nv_bfloat16* __restrict__ h,
    __nv_bfloat16* __restrict__ l, int n4)
{
    int i = blockIdx.x * blockDim.x + threadIdx.x;
    if (i >= n4) return;
    float4 v = ((const float4*)in)[i];
    __nv_bfloat162 h0, h1, l0, l1;
    h0.x = __float2bfloat16(v.x); l0.x = __float2bfloat16(v.x - __bfloat162float(h0.x));
    h0.y = __float2bfloat16(v.y); l0.y = __float2bfloat16(v.y - __bfloat162float(h0.y));
    h1.x = __float2bfloat16(v.z); l1.x = __float2bfloat16(v.z - __bfloat162float(h1.x));
    h1.y = __float2bfloat16(v.w); l1.y = __float2bfloat16(v.w - __bfloat162float(h1.y));
    ((__nv_bfloat162*)h)[2*i]   = h0; ((__nv_bfloat162*)h)[2*i+1] = h1;
    ((__nv_bfloat162*)l)[2*i]   = l0; ((__nv_bfloat162*)l)[2*i+1] = l1;
}

// ==================== bf16x3 GEMM with ldmatrix: C[M,N] = A @ B^T ====================
// R4-proven geometry (GBK=32, RST=40), now with a 3-stage cp.async pipeline.
#define GBM 128
#define GBN 128
#define GBK 32
#define RST 40
#define BUFB (128*RST*2)               // 10240 B per operand buffer
#define STGB (4*BUFB)                  // 40960 B per stage
#define NSTG 3
#define GEMM_SMEM (NSTG*STGB)          // 122880 B

__global__ __launch_bounds__(256) void gemm_bf16x3(
    const __nv_bfloat16* __restrict__ Ah, const __nv_bfloat16* __restrict__ Al,
    const __nv_bfloat16* __restrict__ Bh, const __nv_bfloat16* __restrict__ Bl,
    float* __restrict__ C, int M, int N, int K)
{
    extern __shared__ __align__(16) char dyn[];
    const unsigned sbase = (unsigned)__cvta_generic_to_shared(dyn);

    const int bm = blockIdx.y * GBM, bn = blockIdx.x * GBN;
    const int tid = threadIdx.x, lane = tid & 31, wid = tid >> 5;
    const int wm = (wid >> 2) * 64, wn = (wid & 3) * 32;
    const int g4 = lane >> 2, t4 = lane & 3;

    const int r8 = lane & 7, sel = lane >> 3;
    unsigned aoff[4], boff[2];
#pragma unroll
    for (int mf = 0; mf < 4; mf++)
        aoff[mf] = (unsigned)((wm + mf * 16 + r8 + ((sel & 1) << 3)) * (RST*2)
                              + ((sel >> 1) << 4));
#pragma unroll
    for (int p = 0; p < 2; p++)
        boff[p] = (unsigned)((wn + p * 16 + r8 + ((sel >> 1) << 3)) * (RST*2)
                              + ((sel & 1) << 4));

    float acc[4][4][4];
#pragma unroll
    for (int i = 0; i < 4; i++)
#pragma unroll
        for (int j = 0; j < 4; j++)
#pragma unroll
            for (int r = 0; r < 4; r++) acc[i][j][r] = 0.f;

    const int nk = K / GBK;

#define LOADSTAGE(s, k0) {                                                        \
        unsigned sb = sbase + (s) * STGB;                                         \
        _Pragma("unroll")                                                         \
        for (int rr = 0; rr < 2; rr++) {                                          \
            int idx = tid + rr * 256;                                             \
            int row = idx >> 2, cb = (idx & 3) * 8;                               \
            unsigned so = (unsigned)(row * (RST*2) + cb * 2);                     \
            size_t ga = (size_t)(bm + row) * K + (k0) + cb;                       \
            size_t gb = (size_t)(bn + row) * K + (k0) + cb;                       \
            cp16s(sb            + so, Ah + ga);                                   \
            cp16s(sb +   BUFB   + so, Al + ga);                                   \
            cp16s(sb + 2*BUFB   + so, Bh + gb);                                   \
            cp16s(sb + 3*BUFB   + so, Bl + gb);                                   \
        }                                                                         \
        CP_COMMIT;                                                                \
    }

    LOADSTAGE(0, 0);
    if (nk > 1) LOADSTAGE(1, GBK);

    int sidx = 0;
    for (int kt = 0; kt < nk; kt++) {
        if (kt + 2 < nk) {
            int sn = (sidx + 2 >= NSTG) ? (sidx + 2 - NSTG) : (sidx + 2);
            LOADSTAGE(sn, (kt + 2) * GBK);
            CP_WAIT2;
        } else if (kt + 1 < nk) {
            CP_WAIT1;
        } else {
            CP_WAIT0;
        }
        __syncthreads();

        const unsigned abase = sbase + sidx * STGB;
#pragma unroll
        for (int ks = 0; ks < 2; ks++) {
            const unsigned kb = (unsigned)(ks * 32);
            unsigned ah[4][4], al[4][4], bh[4][2], bl[4][2];
#pragma unroll
            for (int mf = 0; mf < 4; mf++) {
                unsigned ad = abase + aoff[mf] + kb;
                ldm_x4(ah[mf][0], ah[mf][1], ah[mf][2], ah[mf][3], ad);
                ldm_x4(al[mf][0], al[mf][1], al[mf][2], al[mf][3], ad + BUFB);
            }
#pragma unroll
            for (int p = 0; p < 2; p++) {
                unsigned bd = abase + 2*BUFB + boff[p] + kb;
                ldm_x4(bh[2*p][0], bh[2*p][1], bh[2*p+1][0], bh[2*p+1][1], bd);
                ldm_x4(bl[2*p][0], bl[2*p][1], bl[2*p+1][0], bl[2*p+1][1], bd + BUFB);
            }
#pragma unroll
            for (int mf = 0; mf < 4; mf++)
#pragma unroll
                for (int nf = 0; nf < 4; nf++) {
                    mma16(acc[mf][nf], al[mf], bh[nf]);
                    mma16(acc[mf][nf], ah[mf], bl[nf]);
                    mma16(acc[mf][nf], ah[mf], bh[nf]);
                }
        }
        __syncthreads();
        sidx = (sidx + 1 >= NSTG) ? 0 : (sidx + 1);
    }

#pragma unroll
    for (int mf = 0; mf < 4; mf++) {
#pragma unroll
        for (int nf = 0; nf < 4; nf++) {
            int row = bm + wm + mf * 16 + g4;
            int col = bn + wn + nf * 8 + 2 * t4;
            float2 v0 = make_float2(acc[mf][nf][0], acc[mf][nf][1]);
            float2 v1 = make_float2(acc[mf][nf][2], acc[mf][nf][3]);
            *(float2*)(C + (size_t)row * N + col)       = v0;
            *(float2*)(C + (size_t)(row + 8) * N + col) = v1;
        }
    }
#undef LOADSTAGE
}

// ==================== transpose a_w/b_w into wT[2048][32] ====================
__global__ __launch_bounds__(256) void transpose_ab(
    const float* __restrict__ aw, const float* __restrict__ bw,
    float* __restrict__ wt)
{
    int idx = blockIdx.x * 256 + threadIdx.x;   // 65536 total
    int k2 = idx >> 5, j = idx & 31;
    float v = (j < 16) ? aw[(size_t)j * Cn + k2] : bw[(size_t)(j - 16) * Cn + k2];
    wt[(size_t)k2 * 32 + j] = v;
}

// ==================== beta / decay projections (weight-staged) ====================
#define PTM 16
__global__ __launch_bounds__(256) void proj_gb2(
    const float* __restrict__ x, const float* __restrict__ wt,
    const float* __restrict__ bbias, const float* __restrict__ betab,
    const float* __restrict__ alog, const float* __restrict__ dtb,
    float* __restrict__ decout, float* __restrict__ betaout)
{
    __shared__ float ws[256 * 32];
    __shared__ float xs[PTM][256];
    __shared__ float rawm[PTM][32];

    const int tid = threadIdx.x, lane = tid & 31, wid = tid >> 5;
    const int m0 = blockIdx.x * PTM;

    float acc0 = 0.f, acc1 = 0.f;

    for (int kc = 0; kc < Cn / 256; kc++) {
#pragma unroll
        for (int i = 0; i < 32; i++)
            ws[tid + i * 256] = wt[(size_t)kc * 256 * 32 + tid + i * 256];
#pragma unroll
        for (int i = 0; i < 16; i++) {
            int idx = tid + i * 256;
            int tk = idx >> 8, kk = idx & 255;
            xs[tk][kk] = x[(size_t)(m0 + tk) * Cn + kc * 256 + kk];
        }
        __syncthreads();

        const float* w0 = ws + lane;
#pragma unroll 4
        for (int k2 = 0; k2 < 256; k2++) {
            float wv = w0[k2 * 32];
            acc0 = fmaf(xs[2 * wid][k2], wv, acc0);
            acc1 = fmaf(xs[2 * wid + 1][k2], wv, acc1);
        }
        __syncthreads();
    }

    rawm[2 * wid][lane] = acc0;
    rawm[2 * wid + 1][lane] = acc1;
    __syncthreads();

    {
        int token = tid >> 4, hh = tid & 15;
        float sa = rawm[token][hh] + dtb[hh];
        float sp = (sa > 20.f) ? sa : log1pf(expf(sa));
        float g  = -expf(alog[hh]) * sp;
        size_t m = (size_t)(m0 + token);
        decout[m * Hn + hh] = expf(g);
        float sb = rawm[token][16 + hh] + bbias[hh] + betab[hh];
        betaout[m * Hn + hh] = 2.f / (1.f + expf(-sb));
    }
}

// ==================== fused causal conv(4) + silu + l2norm (q/k) ====================
__global__ __launch_bounds__(256) void conv_l2(
    const float* __restrict__ in, int off,
    const float* __restrict__ w, float* __restrict__ out, float scale)
{
    int unit = blockIdx.x * 8 + (threadIdx.x >> 5);   // m*16 + h
    int lane = threadIdx.x & 31;
    int m = unit >> 4, h = unit & 15;
    int t = m & (Tn - 1);
    int ch0 = h * 64;

    float y[2];
#pragma unroll
    for (int half = 0; half < 2; half++) {
        int c = lane + half * 32;
        const float* w4 = w + (size_t)(ch0 + c) * 4;
        const float* p = in + (size_t)m * 2048 + off + ch0 + c;
        float accv = 0.f;
#pragma unroll
        for (int j = 0; j < 4; j++) {
            int tt = t + j - 3;
            if (tt >= 0) accv = fmaf(w4[j], p[(ptrdiff_t)(j - 3) * 2048], accv);
        }
        y[half] = accv / (1.f + expf(-accv));
    }
    float ss = y[0] * y[0] + y[1] * y[1];
#pragma unroll
    for (int o = 16; o; o >>= 1) ss += __shfl_xor_sync(0xffffffffu, ss, o);
    float r = rsqrtf(ss + 1e-6f) * scale;
    out[(size_t)m * KEYD + ch0 + lane]      = y[0] * r;
    out[(size_t)m * KEYD + ch0 + lane + 32] = y[1] * r;
}

// ==================== causal depthwise conv(4) + silu (v) ====================
__global__ void conv_silu(
    const float* __restrict__ in, int ldin, int off,
    const float* __restrict__ w, float* __restrict__ out,
    int CH, int total)
{
    int idx = blockIdx.x * blockDim.x + threadIdx.x;
    if (idx >= total) return;
    int c = idx % CH;
    int t = (idx / CH) % Tn;
    int b = idx / (CH * Tn);
    const float* w4 = w + (size_t)c * 4;
    size_t base = ((size_t)b * Tn) * ldin + off + c;
    float accv = 0.f;
#pragma unroll
    for (int j = 0; j < 4; j++) {
        int tt = t + j - 3;
        if (tt >= 0) accv += w4[j] * in[base + (size_t)tt * ldin];
    }
    out[idx] = accv / (1.f + expf(-accv));
}

// ==================== gated delta rule recurrent scan (SPLIT=2, 1 wave) ====================
#define SPLIT 2
#define CHK 16
__global__ __launch_bounds__(128) void scan_kernel(
    const float* __restrict__ qn, const float* __restrict__ kn,
    const float* __restrict__ vv, const float* __restrict__ dec,
    const float* __restrict__ bet, float* __restrict__ op)
{
    __shared__ __align__(16) float qs[2][CHK][64];
    __shared__ __align__(16) float ks[2][CHK][64];
    __shared__ __align__(16) float vs[2][CHK][64];
    __shared__ float gs[2][CHK], bs[2][CHK];

    const int bid = blockIdx.x;
    const int vh = bid & (SPLIT - 1);
    const int h  = (bid / SPLIT) & (Hn - 1);
    const int b  = bid / (SPLIT * Hn);
    const int tid = threadIdx.x;
    const int jl = tid >> 1, kh = tid & 1;

    float S[32];
#pragma unroll
    for (int i = 0; i < 32; i++) S[i] = 0.f;

#define LOADCHUNK(s, t0) {                                                          \
        _Pragma("unroll")                                                           \
        for (int rr = 0; rr < 2; rr++) {                                            \
            int idx = tid + rr * 128;                                               \
            int row = idx >> 4, q4i = (idx & 15) * 4;                               \
            size_t tb = (size_t)(b * Tn + (t0) + row);                              \
            cp16(&qs[s][row][q4i], qn + (tb * Hn + h) * 64 + q4i);                  \
            cp16(&ks[s][row][q4i], kn + (tb * Hn + h) * 64 + q4i);                  \
            cp16(&vs[s][row][q4i], vv + tb * VALD + h * DVn + vh * 64 + q4i);       \
        }                                                                           \
        if (tid < CHK)            cp4(&gs[s][tid],      dec + (size_t)(b*Tn+(t0)+tid)*Hn + h);        \
        else if (tid < 2*CHK)     cp4(&bs[s][tid-CHK],  bet + (size_t)(b*Tn+(t0)+tid-CHK)*Hn + h);    \
    }

    LOADCHUNK(0, 0);
    CP_COMMIT;

    const int NC = Tn / CHK;
    for (int c = 0; c < NC; c++) {
        const int s = c & 1;
        if (c + 1 < NC) LOADCHUNK(s ^ 1, (c + 1) * CHK);
        CP_COMMIT;
        CP_WAIT1;
        __syncthreads();

        const int t0 = c * CHK;
#pragma unroll 1
        for (int r = 0; r < CHK; r++) {
            const float ge  = gs[s][r];
            const float btc = bs[s][r];
            const float vj  = vs[s][r][jl];
            const float4* kp = (const float4*)&ks[s][r][kh * 32];
            const float4* qp = (const float4*)&qs[s][r][kh * 32];

            float kreg[32];
            float m0 = 0.f, m1 = 0.f, m2 = 0.f, m3 = 0.f;
#pragma unroll
            for (int i = 0; i < 8; i++) {
                float4 k4 = kp[i];
                float s0 = S[4*i+0] * ge, s1 = S[4*i+1] * ge;
                float s2 = S[4*i+2] * ge, s3 = S[4*i+3] * ge;
                m0 += k4.x * s0; m1 += k4.y * s1; m2 += k4.z * s2; m3 += k4.w * s3;
                S[4*i+0] = s0; S[4*i+1] = s1; S[4*i+2] = s2; S[4*i+3] = s3;
                kreg[4*i+0] = k4.x; kreg[4*i+1] = k4.y;
                kreg[4*i+2] = k4.z; kreg[4*i+3] = k4.w;
            }
            float mem = (m0 + m1) + (m2 + m3);
            mem += __shfl_xor_sync(0xffffffffu, mem, 1);
            const float delta = (vj - mem) * btc;

            float o0 = 0.f, o1 = 0.f, o2 = 0.f, o3 = 0.f;
#pragma unroll
            for (int i = 0; i < 8; i++) {
                float4 q4 = qp[i];
                float s0 = S[4*i+0] + kreg[4*i+0] * delta;
                float s1 = S[4*i+1] + kreg[4*i+1] * delta;
                float s2 = S[4*i+2] + kreg[4*i+2] * delta;
                float s3 = S[4*i+3] + kreg[4*i+3] * delta;
                o0 += q4.x * s0; o1 += q4.y * s1; o2 += q4.z * s2; o3 += q4.w * s3;
                S[4*i+0] = s0; S[4*i+1] = s1; S[4*i+2] = s2; S[4*i+3] = s3;
            }
            float ov = (o0 + o1) + (o2 + o3);
            ov += __shfl_xor_sync(0xffffffffu, ov, 1);
            if (kh == 0)
                op[(((size_t)(b * Tn + t0 + r)) * Hn + h) * DVn + vh * 64 + jl] = ov;
        }
        __syncthreads();
    }
#undef LOADCHUNK
}

// ==================== RMS + silu gate, fused bf16 hi/lo split output ====================
__global__ __launch_bounds__(256) void rms_gate_split(
    const float* __restrict__ op, const float* __restrict__ vg,
    __nv_bfloat16* __restrict__ obh, __nv_bfloat16* __restrict__ obl)
{
    int grp = blockIdx.x * 8 + (threadIdx.x >> 5);   // grp = m*16 + h
    int lane = threadIdx.x & 31;
    const float4* src = (const float4*)(op + (size_t)grp * 128);
    float4 o4 = src[lane];
    float ss = o4.x * o4.x + o4.y * o4.y + o4.z * o4.z + o4.w * o4.w;
#pragma unroll
    for (int o = 16; o; o >>= 1) ss += __shfl_xor_sync(0xffffffffu, ss, o);
    float r = rsqrtf(ss * (1.f / 128.f) + 1.1920929e-7f);
    int m = grp >> 4, h = grp & 15;
    const float4* gp = (const float4*)(vg + (size_t)m * 4096 + 2048 + h * 128);
    float4 gg = gp[lane];
    float res[4];
    res[0] = o4.x * r * (gg.x / (1.f + expf(-gg.x)));
    res[1] = o4.y * r * (gg.y / (1.f + expf(-gg.y)));
    res[2] = o4.z * r * (gg.z / (1.f + expf(-gg.z)));
    res[3] = o4.w * r * (gg.w / (1.f + expf(-gg.w)));
    __nv_bfloat16 hv[4], lv[4];
#pragma unroll
    for (int i = 0; i < 4; i++) {
        hv[i] = __float2bfloat16(res[i]);
        lv[i] = __float2bfloat16(res[i] - __bfloat162float(hv[i]));
    }
    size_t off = (size_t)m * 2048 + h * 128 + lane * 4;
    *(uint2*)(obh + off) = *(uint2*)hv;
    *(uint2*)(obl + off) = *(uint2*)lv;
}

// ==================== launch ====================
extern "C" void kernel_launch(void* const* d_in, const int* in_sizes, int n_in,
                              void* d_out, int out_size)
{
    const float* x      = (const float*)d_in[0];
    const float* qk_w   = (const float*)d_in[1];
    const float* vg_w   = (const float*)d_in[2];
    const float* o_w    = (const float*)d_in[3];
    const float* a_w    = (const float*)d_in[4];
    const float* b_w    = (const float*)d_in[5];
    const float* b_bias = (const float*)d_in[6];
    const float* beta_b = (const float*)d_in[7];
    const float* A_log  = (const float*)d_in[8];
    const float* dt_b   = (const float*)d_in[9];
    const float* q_cw   = (const float*)d_in[10];
    const float* k_cw   = (const float*)d_in[11];
    const float* v_cw   = (const float*)d_in[12];
    float* out = (float*)d_out;

    float *qk, *vg, *q, *k, *v, *dc, *bt, *op, *wt;
    __nv_bfloat16 *xh, *xl, *qwh, *qwl, *vwh, *vwl, *owh, *owl, *obh, *obl;
    cudaGetSymbolAddress((void**)&qk, g_qk);
    cudaGetSymbolAddress((void**)&vg, g_vg);
    cudaGetSymbolAddress((void**)&q,  g_q);
    cudaGetSymbolAddress((void**)&k,  g_k);
    cudaGetSymbolAddress((void**)&v,  g_v);
    cudaGetSymbolAddress((void**)&dc, g_dc);
    cudaGetSymbolAddress((void**)&bt, g_bt);
    cudaGetSymbolAddress((void**)&op, g_op);
    cudaGetSymbolAddress((void**)&wt, g_wt);
    cudaGetSymbolAddress((void**)&xh, g_xh);   cudaGetSymbolAddress((void**)&xl, g_xl);
    cudaGetSymbolAddress((void**)&qwh, g_qwh); cudaGetSymbolAddress((void**)&qwl, g_qwl);
    cudaGetSymbolAddress((void**)&vwh, g_vwh); cudaGetSymbolAddress((void**)&vwl, g_vwl);
    cudaGetSymbolAddress((void**)&owh, g_owh); cudaGetSymbolAddress((void**)&owl, g_owl);
    cudaGetSymbolAddress((void**)&obh, g_obh); cudaGetSymbolAddress((void**)&obl, g_obl);

    cudaFuncSetAttribute(gemm_bf16x3, cudaFuncAttributeMaxDynamicSharedMemorySize, GEMM_SMEM);

    // 0) bf16 hi/lo splits + weight transpose
    split_bf16<<<(Mtok*Cn/4 + 255)/256, 256>>>(x, xh, xl, Mtok*Cn/4);
    split_bf16<<<(2048*Cn/4 + 255)/256, 256>>>(qk_w, qwh, qwl, 2048*Cn/4);
    split_bf16<<<(4096*Cn/4 + 255)/256, 256>>>(vg_w, vwh, vwl, 4096*Cn/4);
    split_bf16<<<(2048*Cn/4 + 255)/256, 256>>>(o_w,  owh, owl, 2048*Cn/4);
    transpose_ab<<<Cn*32/256, 256>>>(a_w, b_w, wt);

    // 1) big projections (separate launches — proven)
    gemm_bf16x3<<<dim3(2048/GBN, Mtok/GBM), 256, GEMM_SMEM>>>(xh, xl, qwh, qwl, qk, Mtok, 2048, Cn);
    gemm_bf16x3<<<dim3(4096/GBN, Mtok/GBM), 256, GEMM_SMEM>>>(xh, xl, vwh, vwl, vg, Mtok, 4096, Cn);

    // 2) beta + decay (weight-staged)
    proj_gb2<<<Mtok/PTM, 256>>>(x, wt, b_bias, beta_b, A_log, dt_b, dc, bt);

    // 3) fused conv+silu+l2norm for q,k; conv+silu for v
    conv_l2<<<Mtok * Hn / 8, 256>>>(qk, 0,    q_cw, q, 0.125f);
    conv_l2<<<Mtok * Hn / 8, 256>>>(qk, 1024, k_cw, k, 1.0f);
    {
        int tv = Mtok * VALD;
        conv_silu<<<(tv + 255) / 256, 256>>>(vg, 4096, 0, v_cw, v, VALD, tv);
    }

    // 4) recurrent scan (SPLIT=2 -> 128 blocks, single wave)
    scan_kernel<<<Bsz * Hn * SPLIT, 128>>>(q, k, v, dc, bt, op);

    // 5) RMS + gate + fused bf16 split
    rms_gate_split<<<Mtok * Hn / 8, 256>>>(op, vg, obh, obl);

    // 6) output projection
    gemm_bf16x3<<<dim3(2048/GBN, Mtok/GBM), 256, GEMM_SMEM>>>(obh, obl, owh, owl, out, Mtok, 2048, Cn);
}

// round 11
// speedup vs baseline: 1.1330x; 1.1330x over previous
#include <cuda_runtime.h>
#include <cuda_bf16.h>
#include <math.h>
#include <stdint.h>

// Problem constants
#define Bsz 4
#define Tn 2048
#define Cn 2048
#define Hn 16
#define DKn 64
#define DVn 128
#define Mtok (Bsz*Tn)          // 8192
#define KEYD (Hn*DKn)          // 1024
#define VALD (Hn*DVn)          // 2048

// -------------------- scratch (device globals, no allocation) --------------------
__device__ float g_qk[(size_t)Mtok*2048];   // x @ qk_w^T
__device__ float g_vg[(size_t)Mtok*4096];   // x @ vg_w^T
__device__ float g_q [(size_t)Mtok*KEYD];
__device__ float g_k [(size_t)Mtok*KEYD];
__device__ float g_v [(size_t)Mtok*VALD];
__device__ float g_dc[(size_t)Mtok*Hn];
__device__ float g_bt[(size_t)Mtok*Hn];
__device__ float g_op[(size_t)Mtok*VALD];
__device__ float g_wt[(size_t)Cn*32];       // transposed [a_w;b_w]

// bf16 hi/lo split operands for the tensor GEMMs
__device__ __nv_bfloat16 g_xh [(size_t)Mtok*Cn],  g_xl [(size_t)Mtok*Cn];
__device__ __nv_bfloat16 g_qwh[(size_t)2048*Cn],  g_qwl[(size_t)2048*Cn];
__device__ __nv_bfloat16 g_vwh[(size_t)4096*Cn],  g_vwl[(size_t)4096*Cn];
__device__ __nv_bfloat16 g_owh[(size_t)2048*Cn],  g_owl[(size_t)2048*Cn];
__device__ __nv_bfloat16 g_obh[(size_t)Mtok*VALD], g_obl[(size_t)Mtok*VALD];

// -------------------- cp.async helpers --------------------
__device__ __forceinline__ void cp16(void* s, const void* g) {
    unsigned ss = (unsigned)__cvta_generic_to_shared(s);
    asm volatile("cp.async.cg.shared.global [%0], [%1], 16;\n" :: "r"(ss), "l"(g));
}
__device__ __forceinline__ void cp16s(unsigned saddr, const void* g) {
    asm volatile("cp.async.cg.shared.global [%0], [%1], 16;\n" :: "r"(saddr), "l"(g));
}
__device__ __forceinline__ void cp4(void* s, const void* g) {
    unsigned ss = (unsigned)__cvta_generic_to_shared(s);
    asm volatile("cp.async.ca.shared.global [%0], [%1], 4;\n" :: "r"(ss), "l"(g));
}
#define CP_COMMIT asm volatile("cp.async.commit_group;\n" ::: "memory")
#define CP_WAIT1  asm volatile("cp.async.wait_group 1;\n" ::: "memory")
#define CP_WAIT0  asm volatile("cp.async.wait_group 0;\n" ::: "memory")

// bf16 mma m16n8k16
__device__ __forceinline__ void mma16(float* c, const unsigned* a, const unsigned* b) {
    asm volatile(
        "mma.sync.aligned.m16n8k16.row.col.f32.bf16.bf16.f32 "
        "{%0,%1,%2,%3},{%4,%5,%6,%7},{%8,%9},{%0,%1,%2,%3};\n"
        : "+f"(c[0]), "+f"(c[1]), "+f"(c[2]), "+f"(c[3])
        : "r"(a[0]), "r"(a[1]), "r"(a[2]), "r"(a[3]), "r"(b[0]), "r"(b[1]));
}

__device__ __forceinline__ void ldm_x4(unsigned& r0, unsigned& r1,
                                       unsigned& r2, unsigned& r3, unsigned addr) {
    asm volatile("ldmatrix.sync.aligned.m8n8.x4.shared.b16 {%0,%1,%2,%3}, [%4];"
                 : "=r"(r0), "=r"(r1), "=r"(r2), "=r"(r3) : "r"(addr));
}

// ==================== bf16 hi/lo split ====================
__global__ __launch_bounds__(256) void split_bf16(
    const float* __restrict__ in, __nv_bfloat16* __restrict__ h,
    __nv_bfloat16* __restrict__ l, int n4)
{
    int i = blockIdx.x * blockDim.x + threadIdx.x;
    if (i >= n4) return;
    float4 v = ((const float4*)in)[i];
    __nv_bfloat162 h0, h1, l0, l1;
    h0.x = __float2bfloat16(v.x); l0.x = __float2bfloat16(v.x - __bfloat162float(h0.x));
    h0.y = __float2bfloat16(v.y); l0.y = __float2bfloat16(v.y - __bfloat162float(h0.y));
    h1.x = __float2bfloat16(v.z); l1.x = __float2bfloat16(v.z - __bfloat162float(h1.x));
    h1.y = __float2bfloat16(v.w); l1.y = __float2bfloat16(v.w - __bfloat162float(h1.y));
    ((__nv_bfloat162*)h)[2*i]   = h0; ((__nv_bfloat162*)h)[2*i+1] = h1;
    ((__nv_bfloat162*)l)[2*i]   = l0; ((__nv_bfloat162*)l)[2*i+1] = l1;
}

// ==================== bf16x3 GEMM with ldmatrix: C[M,N] = A @ B^T ====================
// R9-proven: GBK=32, RST=40, 2-stage cp.async pipeline. LOCKED.
#define GBM 128
#define GBN 128
#define GBK 32
#define RST 40
#define BUFB (128*RST*2)               // 10240 B per operand buffer
#define STGB (4*BUFB)                  // 40960 B per stage
#define GEMM_SMEM (2*STGB)             // 81920 B

__global__ __launch_bounds__(256) void gemm_bf16x3(
    const __nv_bfloat16* __restrict__ Ah, const __nv_bfloat16* __restrict__ Al,
    const __nv_bfloat16* __restrict__ Bh, const __nv_bfloat16* __restrict__ Bl,
    float* __restrict__ C, int M, int N, int K)
{
    extern __shared__ __align__(16) char dyn[];
    const unsigned sbase = (unsigned)__cvta_generic_to_shared(dyn);

    const int bm = blockIdx.y * GBM, bn = blockIdx.x * GBN;
    const int tid = threadIdx.x, lane = tid & 31, wid = tid >> 5;
    const int wm = (wid >> 2) * 64, wn = (wid & 3) * 32;
    const int g4 = lane >> 2, t4 = lane & 3;

    const int r8 = lane & 7, sel = lane >> 3;
    unsigned aoff[4], boff[2];
#pragma unroll
    for (int mf = 0; mf < 4; mf++)
        aoff[mf] = (unsigned)((wm + mf * 16 + r8 + ((sel & 1) << 3)) * (RST*2)
                              + ((sel >> 1) << 4));
#pragma unroll
    for (int p = 0; p < 2; p++)
        boff[p] = (unsigned)((wn + p * 16 + r8 + ((sel >> 1) << 3)) * (RST*2)
                              + ((sel & 1) << 4));

    float acc[4][4][4];
#pragma unroll
    for (int i = 0; i < 4; i++)
#pragma unroll
        for (int j = 0; j < 4; j++)
#pragma unroll
            for (int r = 0; r < 4; r++) acc[i][j][r] = 0.f;

    const int nk = K / GBK;

#define LOADSTAGE(s, k0) {                                                        \
        unsigned sb = sbase + (s) * STGB;                                         \
        _Pragma("unroll")                                                         \
        for (int rr = 0; rr < 2; rr++) {                                          \
            int idx = tid + rr * 256;                                             \
            int row = idx >> 2, cb = (idx & 3) * 8;                               \
            unsigned so = (unsigned)(row * (RST*2) + cb * 2);                     \
            size_t ga = (size_t)(bm + row) * K + (k0) + cb;                       \
            size_t gb = (size_t)(bn + row) * K + (k0) + cb;                       \
            cp16s(sb            + so, Ah + ga);                                   \
            cp16s(sb +   BUFB   + so, Al + ga);                                   \
            cp16s(sb + 2*BUFB   + so, Bh + gb);                                   \
            cp16s(sb + 3*BUFB   + so, Bl + gb);                                   \
        }                                                                         \
    }

    LOADSTAGE(0, 0);
    CP_COMMIT;

    for (int kt = 0; kt < nk; kt++) {
        const int s = kt & 1;
        if (kt + 1 < nk) LOADSTAGE(s ^ 1, (kt + 1) * GBK);
        CP_COMMIT;
        CP_WAIT1;
        __syncthreads();

        const unsigned abase = sbase + s * STGB;
#pragma unroll
        for (int ks = 0; ks < 2; ks++) {
            const unsigned kb = (unsigned)(ks * 32);
            unsigned ah[4][4], al[4][4], bh[4][2], bl[4][2];
#pragma unroll
            for (int mf = 0; mf < 4; mf++) {
                unsigned ad = abase + aoff[mf] + kb;
                ldm_x4(ah[mf][0], ah[mf][1], ah[mf][2], ah[mf][3], ad);
                ldm_x4(al[mf][0], al[mf][1], al[mf][2], al[mf][3], ad + BUFB);
            }
#pragma unroll
            for (int p = 0; p < 2; p++) {
                unsigned bd = abase + 2*BUFB + boff[p] + kb;
                ldm_x4(bh[2*p][0], bh[2*p][1], bh[2*p+1][0], bh[2*p+1][1], bd);
                ldm_x4(bl[2*p][0], bl[2*p][1], bl[2*p+1][0], bl[2*p+1][1], bd + BUFB);
            }
#pragma unroll
            for (int mf = 0; mf < 4; mf++)
#pragma unroll
                for (int nf = 0; nf < 4; nf++) {
                    mma16(acc[mf][nf], al[mf], bh[nf]);
                    mma16(acc[mf][nf], ah[mf], bl[nf]);
                    mma16(acc[mf][nf], ah[mf], bh[nf]);
                }
        }
        __syncthreads();
    }

#pragma unroll
    for (int mf = 0; mf < 4; mf++) {
#pragma unroll
        for (int nf = 0; nf < 4; nf++) {
            int row = bm + wm + mf * 16 + g4;
            int col = bn + wn + nf * 8 + 2 * t4;
            float2 v0 = make_float2(acc[mf][nf][0], acc[mf][nf][1]);
            float2 v1 = make_float2(acc[mf][nf][2], acc[mf][nf][3]);
            *(float2*)(C + (size_t)row * N + col)       = v0;
            *(float2*)(C + (size_t)(row + 8) * N + col) = v1;
        }
    }
#undef LOADSTAGE
}

// ==================== transpose a_w/b_w into wT[2048][32] ====================
__global__ __launch_bounds__(256) void transpose_ab(
    const float* __restrict__ aw, const float* __restrict__ bw,
    float* __restrict__ wt)
{
    int idx = blockIdx.x * 256 + threadIdx.x;   // 65536 total
    int k2 = idx >> 5, j = idx & 31;
    float v = (j < 16) ? aw[(size_t)j * Cn + k2] : bw[(size_t)(j - 16) * Cn + k2];
    wt[(size_t)k2 * 32 + j] = v;
}

// ==================== beta / decay projections (weight-staged) ====================
#define PTM 16
__global__ __launch_bounds__(256) void proj_gb2(
    const float* __restrict__ x, const float* __restrict__ wt,
    const float* __restrict__ bbias, const float* __restrict__ betab,
    const float* __restrict__ alog, const float* __restrict__ dtb,
    float* __restrict__ decout, float* __restrict__ betaout)
{
    __shared__ float ws[256 * 32];
    __shared__ float xs[PTM][256];
    __shared__ float rawm[PTM][32];

    const int tid = threadIdx.x, lane = tid & 31, wid = tid >> 5;
    const int m0 = blockIdx.x * PTM;

    float acc0 = 0.f, acc1 = 0.f;

    for (int kc = 0; kc < Cn / 256; kc++) {
#pragma unroll
        for (int i = 0; i < 32; i++)
            ws[tid + i * 256] = wt[(size_t)kc * 256 * 32 + tid + i * 256];
#pragma unroll
        for (int i = 0; i < 16; i++) {
            int idx = tid + i * 256;
            int tk = idx >> 8, kk = idx & 255;
            xs[tk][kk] = x[(size_t)(m0 + tk) * Cn + kc * 256 + kk];
        }
        __syncthreads();

        const float* w0 = ws + lane;
#pragma unroll 4
        for (int k2 = 0; k2 < 256; k2++) {
            float wv = w0[k2 * 32];
            acc0 = fmaf(xs[2 * wid][k2], wv, acc0);
            acc1 = fmaf(xs[2 * wid + 1][k2], wv, acc1);
        }
        __syncthreads();
    }

    rawm[2 * wid][lane] = acc0;
    rawm[2 * wid + 1][lane] = acc1;
    __syncthreads();

    {
        int token = tid >> 4, hh = tid & 15;
        float sa = rawm[token][hh] + dtb[hh];
        float sp = (sa > 20.f) ? sa : log1pf(expf(sa));
        float g  = -expf(alog[hh]) * sp;
        size_t m = (size_t)(m0 + token);
        decout[m * Hn + hh] = expf(g);
        float sb = rawm[token][16 + hh] + bbias[hh] + betab[hh];
        betaout[m * Hn + hh] = 2.f / (1.f + expf(-sb));
    }
}

// ==================== fused causal conv(4) + silu + l2norm (q/k) ====================
__global__ __launch_bounds__(256) void conv_l2(
    const float* __restrict__ in, int off,
    const float* __restrict__ w, float* __restrict__ out, float scale)
{
    int unit = blockIdx.x * 8 + (threadIdx.x >> 5);   // m*16 + h
    int lane = threadIdx.x & 31;
    int m = unit >> 4, h = unit & 15;
    int t = m & (Tn - 1);
    int ch0 = h * 64;

    float y[2];
#pragma unroll
    for (int half = 0; half < 2; half++) {
        int c = lane + half * 32;
        const float* w4 = w + (size_t)(ch0 + c) * 4;
        const float* p = in + (size_t)m * 2048 + off + ch0 + c;
        float accv = 0.f;
#pragma unroll
        for (int j = 0; j < 4; j++) {
            int tt = t + j - 3;
            if (tt >= 0) accv = fmaf(w4[j], p[(ptrdiff_t)(j - 3) * 2048], accv);
        }
        y[half] = accv / (1.f + expf(-accv));
    }
    float ss = y[0] * y[0] + y[1] * y[1];
#pragma unroll
    for (int o = 16; o; o >>= 1) ss += __shfl_xor_sync(0xffffffffu, ss, o);
    float r = rsqrtf(ss + 1e-6f) * scale;
    out[(size_t)m * KEYD + ch0 + lane]      = y[0] * r;
    out[(size_t)m * KEYD + ch0 + lane + 32] = y[1] * r;
}

// ==================== causal depthwise conv(4) + silu (v) ====================
__global__ void conv_silu(
    const float* __restrict__ in, int ldin, int off,
    const float* __restrict__ w, float* __restrict__ out,
    int CH, int total)
{
    int idx = blockIdx.x * blockDim.x + threadIdx.x;
    if (idx >= total) return;
    int c = idx % CH;
    int t = (idx / CH) % Tn;
    int b = idx / (CH * Tn);
    const float* w4 = w + (size_t)c * 4;
    size_t base = ((size_t)b * Tn) * ldin + off + c;
    float accv = 0.f;
#pragma unroll
    for (int j = 0; j < 4; j++) {
        int tt = t + j - 3;
        if (tt >= 0) accv += w4[j] * in[base + (size_t)tt * ldin];
    }
    out[idx] = accv / (1.f + expf(-accv));
}

// ==================== gated delta rule recurrent scan ====================
// SPLIT=2 -> 128 blocks (1 wave). NOW 256 threads: 2 warps/SMSP to hide
// the serial-chain bubbles. Thread (jl = tid>>2, kh = tid&3) owns
// S[k = kh*16 .. kh*16+15][col jl].
#define SPLIT 2
#define CHK 16
__global__ __launch_bounds__(256) void scan_kernel(
    const float* __restrict__ qn, const float* __restrict__ kn,
    const float* __restrict__ vv, const float* __restrict__ dec,
    const float* __restrict__ bet, float* __restrict__ op)
{
    __shared__ __align__(16) float qs[2][CHK][64];
    __shared__ __align__(16) float ks[2][CHK][64];
    __shared__ __align__(16) float vs[2][CHK][64];
    __shared__ float gs[2][CHK], bs[2][CHK];

    const int bid = blockIdx.x;
    const int vh = bid & (SPLIT - 1);
    const int h  = (bid / SPLIT) & (Hn - 1);
    const int b  = bid / (SPLIT * Hn);
    const int tid = threadIdx.x;
    const int jl = tid >> 2, kh = tid & 3;

    float S[16];
#pragma unroll
    for (int i = 0; i < 16; i++) S[i] = 0.f;

    // 256 threads: each loads one float4 per buffer (CHK*64 = 1024 floats = 256 float4)
#define LOADCHUNK(s, t0) {                                                          \
        {                                                                           \
            int row = tid >> 4, q4i = (tid & 15) * 4;                               \
            size_t tb = (size_t)(b * Tn + (t0) + row);                              \
            cp16(&qs[s][row][q4i], qn + (tb * Hn + h) * 64 + q4i);                  \
            cp16(&ks[s][row][q4i], kn + (tb * Hn + h) * 64 + q4i);                  \
            cp16(&vs[s][row][q4i], vv + tb * VALD + h * DVn + vh * 64 + q4i);       \
        }                                                                           \
        if (tid < CHK)            cp4(&gs[s][tid],      dec + (size_t)(b*Tn+(t0)+tid)*Hn + h);        \
        else if (tid < 2*CHK)     cp4(&bs[s][tid-CHK],  bet + (size_t)(b*Tn+(t0)+tid-CHK)*Hn + h);    \
    }

    LOADCHUNK(0, 0);
    CP_COMMIT;

    const int NC = Tn / CHK;
    for (int c = 0; c < NC; c++) {
        const int s = c & 1;
        if (c + 1 < NC) LOADCHUNK(s ^ 1, (c + 1) * CHK);
        CP_COMMIT;
        CP_WAIT1;
        __syncthreads();

        const int t0 = c * CHK;
#pragma unroll 1
        for (int r = 0; r < CHK; r++) {
            const float ge  = gs[s][r];
            const float btc = bs[s][r];
            const float vj  = vs[s][r][jl];
            const float4* kp = (const float4*)&ks[s][r][kh * 16];
            const float4* qp = (const float4*)&qs[s][r][kh * 16];

            float kreg[16];
            float m0 = 0.f, m1 = 0.f, m2 = 0.f, m3 = 0.f;
#pragma unroll
            for (int i = 0; i < 4; i++) {
                float4 k4 = kp[i];
                float s0 = S[4*i+0] * ge, s1 = S[4*i+1] * ge;
                float s2 = S[4*i+2] * ge, s3 = S[4*i+3] * ge;
                m0 += k4.x * s0; m1 += k4.y * s1; m2 += k4.z * s2; m3 += k4.w * s3;
                S[4*i+0] = s0; S[4*i+1] = s1; S[4*i+2] = s2; S[4*i+3] = s3;
                kreg[4*i+0] = k4.x; kreg[4*i+1] = k4.y;
                kreg[4*i+2] = k4.z; kreg[4*i+3] = k4.w;
            }
            float mem = (m0 + m1) + (m2 + m3);
            mem += __shfl_xor_sync(0xffffffffu, mem, 1);
            mem += __shfl_xor_sync(0xffffffffu, mem, 2);
            const float delta = (vj - mem) * btc;

            float o0 = 0.f, o1 = 0.f, o2 = 0.f, o3 = 0.f;
#pragma unroll
            for (int i = 0; i < 4; i++) {
                float4 q4 = qp[i];
                float s0 = S[4*i+0] + kreg[4*i+0] * delta;
                float s1 = S[4*i+1] + kreg[4*i+1] * delta;
                float s2 = S[4*i+2] + kreg[4*i+2] * delta;
                float s3 = S[4*i+3] + kreg[4*i+3] * delta;
                o0 += q4.x * s0; o1 += q4.y * s1; o2 += q4.z * s2; o3 += q4.w * s3;
                S[4*i+0] = s0; S[4*i+1] = s1; S[4*i+2] = s2; S[4*i+3] = s3;
            }
            float ov = (o0 + o1) + (o2 + o3);
            ov += __shfl_xor_sync(0xffffffffu, ov, 1);
            ov += __shfl_xor_sync(0xffffffffu, ov, 2);
            if (kh == 0)
                op[(((size_t)(b * Tn + t0 + r)) * Hn + h) * DVn + vh * 64 + jl] = ov;
        }
        __syncthreads();
    }
#undef LOADCHUNK
}

// ==================== RMS + silu gate, fused bf16 hi/lo split output ====================
__global__ __launch_bounds__(256) void rms_gate_split(
    const float* __restrict__ op, const float* __restrict__ vg,
    __nv_bfloat16* __restrict__ obh, __nv_bfloat16* __restrict__ obl)
{
    int grp = blockIdx.x * 8 + (threadIdx.x >> 5);   // grp = m*16 + h
    int lane = threadIdx.x & 31;
    const float4* src = (const float4*)(op + (size_t)grp * 128);
    float4 o4 = src[lane];
    float ss = o4.x * o4.x + o4.y * o4.y + o4.z * o4.z + o4.w * o4.w;
#pragma unroll
    for (int o = 16; o; o >>= 1) ss += __shfl_xor_sync(0xffffffffu, ss, o);
    float r = rsqrtf(ss * (1.f / 128.f) + 1.1920929e-7f);
    int m = grp >> 4, h = grp & 15;
    const float4* gp = (const float4*)(vg + (size_t)m * 4096 + 2048 + h * 128);
    float4 gg = gp[lane];
    float res[4];
    res[0] = o4.x * r * (gg.x / (1.f + expf(-gg.x)));
    res[1] = o4.y * r * (gg.y / (1.f + expf(-gg.y)));
    res[2] = o4.z * r * (gg.z / (1.f + expf(-gg.z)));
    res[3] = o4.w * r * (gg.w / (1.f + expf(-gg.w)));
    __nv_bfloat16 hv[4], lv[4];
#pragma unroll
    for (int i = 0; i < 4; i++) {
        hv[i] = __float2bfloat16(res[i]);
        lv[i] = __float2bfloat16(res[i] - __bfloat162float(hv[i]));
    }
    size_t off = (size_t)m * 2048 + h * 128 + lane * 4;
    *(uint2*)(obh + off) = *(uint2*)hv;
    *(uint2*)(obl + off) = *(uint2*)lv;
}

// ==================== launch ====================
extern "C" void kernel_launch(void* const* d_in, const int* in_sizes, int n_in,
                              void* d_out, int out_size)
{
    const float* x      = (const float*)d_in[0];
    const float* qk_w   = (const float*)d_in[1];
    const float* vg_w   = (const float*)d_in[2];
    const float* o_w    = (const float*)d_in[3];
    const float* a_w    = (const float*)d_in[4];
    const float* b_w    = (const float*)d_in[5];
    const float* b_bias = (const float*)d_in[6];
    const float* beta_b = (const float*)d_in[7];
    const float* A_log  = (const float*)d_in[8];
    const float* dt_b   = (const float*)d_in[9];
    const float* q_cw   = (const float*)d_in[10];
    const float* k_cw   = (const float*)d_in[11];
    const float* v_cw   = (const float*)d_in[12];
    float* out = (float*)d_out;

    float *qk, *vg, *q, *k, *v, *dc, *bt, *op, *wt;
    __nv_bfloat16 *xh, *xl, *qwh, *qwl, *vwh, *vwl, *owh, *owl, *obh, *obl;
    cudaGetSymbolAddress((void**)&qk, g_qk);
    cudaGetSymbolAddress((void**)&vg, g_vg);
    cudaGetSymbolAddress((void**)&q,  g_q);
    cudaGetSymbolAddress((void**)&k,  g_k);
    cudaGetSymbolAddress((void**)&v,  g_v);
    cudaGetSymbolAddress((void**)&dc, g_dc);
    cudaGetSymbolAddress((void**)&bt, g_bt);
    cudaGetSymbolAddress((void**)&op, g_op);
    cudaGetSymbolAddress((void**)&wt, g_wt);
    cudaGetSymbolAddress((void**)&xh, g_xh);   cudaGetSymbolAddress((void**)&xl, g_xl);
    cudaGetSymbolAddress((void**)&qwh, g_qwh); cudaGetSymbolAddress((void**)&qwl, g_qwl);
    cudaGetSymbolAddress((void**)&vwh, g_vwh); cudaGetSymbolAddress((void**)&vwl, g_vwl);
    cudaGetSymbolAddress((void**)&owh, g_owh); cudaGetSymbolAddress((void**)&owl, g_owl);
    cudaGetSymbolAddress((void**)&obh, g_obh); cudaGetSymbolAddress((void**)&obl, g_obl);

    cudaFuncSetAttribute(gemm_bf16x3, cudaFuncAttributeMaxDynamicSharedMemorySize, GEMM_SMEM);

    // 0) bf16 hi/lo splits + weight transpose
    split_bf16<<<(Mtok*Cn/4 + 255)/256, 256>>>(x, xh, xl, Mtok*Cn/4);
    split_bf16<<<(2048*Cn/4 + 255)/256, 256>>>(qk_w, qwh, qwl, 2048*Cn/4);
    split_bf16<<<(4096*Cn/4 + 255)/256, 256>>>(vg_w, vwh, vwl, 4096*Cn/4);
    split_bf16<<<(2048*Cn/4 + 255)/256, 256>>>(o_w,  owh, owl, 2048*Cn/4);
    transpose_ab<<<Cn*32/256, 256>>>(a_w, b_w, wt);

    // 1) big projections (separate launches, 2-stage pipeline — proven)
    gemm_bf16x3<<<dim3(2048/GBN, Mtok/GBM), 256, GEMM_SMEM>>>(xh, xl, qwh, qwl, qk, Mtok, 2048, Cn);
    gemm_bf16x3<<<dim3(4096/GBN, Mtok/GBM), 256, GEMM_SMEM>>>(xh, xl, vwh, vwl, vg, Mtok, 4096, Cn);

    // 2) beta + decay (weight-staged)
    proj_gb2<<<Mtok/PTM, 256>>>(x, wt, b_bias, beta_b, A_log, dt_b, dc, bt);

    // 3) fused conv+silu+l2norm for q,k; conv+silu for v
    conv_l2<<<Mtok * Hn / 8, 256>>>(qk, 0,    q_cw, q, 0.125f);
    conv_l2<<<Mtok * Hn / 8, 256>>>(qk, 1024, k_cw, k, 1.0f);
    {
        int tv = Mtok * VALD;
        conv_silu<<<(tv + 255) / 256, 256>>>(vg, 4096, 0, v_cw, v, VALD, tv);
    }

    // 4) recurrent scan (SPLIT=2 -> 128 blocks, 256 threads, single wave)
    scan_kernel<<<Bsz * Hn * SPLIT, 256>>>(q, k, v, dc, bt, op);

    // 5) RMS + gate + fused bf16 split
    rms_gate_split<<<Mtok * Hn / 8, 256>>>(op, vg, obh, obl);

    // 6) output projection
    gemm_bf16x3<<<dim3(2048/GBN, Mtok/GBM), 256, GEMM_SMEM>>>(obh, obl, owh, owl, out, Mtok, 2048, Cn);
}

// round 12
// speedup vs baseline: 1.2194x; 1.0763x over previous
#include <cuda_runtime.h>
#include <cuda_bf16.h>
#include <math.h>
#include <stdint.h>

// Problem constants
#define Bsz 4
#define Tn 2048
#define Cn 2048
#define Hn 16
#define DKn 64
#define DVn 128
#define Mtok (Bsz*Tn)          // 8192
#define KEYD (Hn*DKn)          // 1024
#define VALD (Hn*DVn)          // 2048

// -------------------- scratch (device globals, no allocation) --------------------
__device__ float g_qk[(size_t)Mtok*2048];   // x @ qk_w^T
__device__ float g_vg[(size_t)Mtok*4096];   // x @ vg_w^T
__device__ float g_q [(size_t)Mtok*KEYD];
__device__ float g_k [(size_t)Mtok*KEYD];
__device__ float g_v [(size_t)Mtok*VALD];
__device__ float g_dc[(size_t)Mtok*Hn];
__device__ float g_bt[(size_t)Mtok*Hn];
__device__ float g_op[(size_t)Mtok*VALD];
__device__ float g_wt[(size_t)Cn*32];       // transposed [a_w;b_w]

// bf16 hi/lo split operands for the tensor GEMMs
__device__ __nv_bfloat16 g_xh [(size_t)Mtok*Cn],  g_xl [(size_t)Mtok*Cn];
__device__ __nv_bfloat16 g_qwh[(size_t)2048*Cn],  g_qwl[(size_t)2048*Cn];
__device__ __nv_bfloat16 g_vwh[(size_t)4096*Cn],  g_vwl[(size_t)4096*Cn];
__device__ __nv_bfloat16 g_owh[(size_t)2048*Cn],  g_owl[(size_t)2048*Cn];
__device__ __nv_bfloat16 g_obh[(size_t)Mtok*VALD], g_obl[(size_t)Mtok*VALD];

// -------------------- cp.async helpers --------------------
__device__ __forceinline__ void cp16(void* s, const void* g) {
    unsigned ss = (unsigned)__cvta_generic_to_shared(s);
    asm volatile("cp.async.cg.shared.global [%0], [%1], 16;\n" :: "r"(ss), "l"(g));
}
__device__ __forceinline__ void cp16s(unsigned saddr, const void* g) {
    asm volatile("cp.async.cg.shared.global [%0], [%1], 16;\n" :: "r"(saddr), "l"(g));
}
__device__ __forceinline__ void cp4(void* s, const void* g) {
    unsigned ss = (unsigned)__cvta_generic_to_shared(s);
    asm volatile("cp.async.ca.shared.global [%0], [%1], 4;\n" :: "r"(ss), "l"(g));
}
#define CP_COMMIT asm volatile("cp.async.commit_group;\n" ::: "memory")
#define CP_WAIT1  asm volatile("cp.async.wait_group 1;\n" ::: "memory")
#define CP_WAIT0  asm volatile("cp.async.wait_group 0;\n" ::: "memory")

// -------------------- packed f32x2 helpers (sm_100+ family) --------------------
typedef unsigned long long u64t;
__device__ __forceinline__ u64t pack2(float lo, float hi) {
    u64t r; asm("mov.b64 %0, {%1, %2};" : "=l"(r) : "f"(lo), "f"(hi)); return r;
}
__device__ __forceinline__ void unpack2(u64t v, float& lo, float& hi) {
    asm("mov.b64 {%0, %1}, %2;" : "=f"(lo), "=f"(hi) : "l"(v));
}
__device__ __forceinline__ u64t mul2(u64t a, u64t b) {
    u64t r; asm("mul.rn.f32x2 %0, %1, %2;" : "=l"(r) : "l"(a), "l"(b)); return r;
}
__device__ __forceinline__ u64t fma2(u64t a, u64t b, u64t c) {
    u64t r; asm("fma.rn.f32x2 %0, %1, %2, %3;" : "=l"(r) : "l"(a), "l"(b), "l"(c)); return r;
}

// bf16 mma m16n8k16
__device__ __forceinline__ void mma16(float* c, const unsigned* a, const unsigned* b) {
    asm volatile(
        "mma.sync.aligned.m16n8k16.row.col.f32.bf16.bf16.f32 "
        "{%0,%1,%2,%3},{%4,%5,%6,%7},{%8,%9},{%0,%1,%2,%3};\n"
        : "+f"(c[0]), "+f"(c[1]), "+f"(c[2]), "+f"(c[3])
        : "r"(a[0]), "r"(a[1]), "r"(a[2]), "r"(a[3]), "r"(b[0]), "r"(b[1]));
}

__device__ __forceinline__ void ldm_x4(unsigned& r0, unsigned& r1,
                                       unsigned& r2, unsigned& r3, unsigned addr) {
    asm volatile("ldmatrix.sync.aligned.m8n8.x4.shared.b16 {%0,%1,%2,%3}, [%4];"
                 : "=r"(r0), "=r"(r1), "=r"(r2), "=r"(r3) : "r"(addr));
}

// ==================== bf16 hi/lo split ====================
__global__ __launch_bounds__(256) void split_bf16(
    const float* __restrict__ in, __nv_bfloat16* __restrict__ h,
    __nv_bfloat16* __restrict__ l, int n4)
{
    int i = blockIdx.x * blockDim.x + threadIdx.x;
    if (i >= n4) return;
    float4 v = ((const float4*)in)[i];
    __nv_bfloat162 h0, h1, l0, l1;
    h0.x = __float2bfloat16(v.x); l0.x = __float2bfloat16(v.x - __bfloat162float(h0.x));
    h0.y = __float2bfloat16(v.y); l0.y = __float2bfloat16(v.y - __bfloat162float(h0.y));
    h1.x = __float2bfloat16(v.z); l1.x = __float2bfloat16(v.z - __bfloat162float(h1.x));
    h1.y = __float2bfloat16(v.w); l1.y = __float2bfloat16(v.w - __bfloat162float(h1.y));
    ((__nv_bfloat162*)h)[2*i]   = h0; ((__nv_bfloat162*)h)[2*i+1] = h1;
    ((__nv_bfloat162*)l)[2*i]   = l0; ((__nv_bfloat162*)l)[2*i+1] = l1;
}

// ==================== bf16x3 GEMM with ldmatrix: C[M,N] = A @ B^T ====================
// LOCKED: GBK=32, RST=40, 2-stage cp.async pipeline.
#define GBM 128
#define GBN 128
#define GBK 32
#define RST 40
#define BUFB (128*RST*2)               // 10240 B per operand buffer
#define STGB (4*BUFB)                  // 40960 B per stage
#define GEMM_SMEM (2*STGB)             // 81920 B

__global__ __launch_bounds__(256) void gemm_bf16x3(
    const __nv_bfloat16* __restrict__ Ah, const __nv_bfloat16* __restrict__ Al,
    const __nv_bfloat16* __restrict__ Bh, const __nv_bfloat16* __restrict__ Bl,
    float* __restrict__ C, int M, int N, int K)
{
    extern __shared__ __align__(16) char dyn[];
    const unsigned sbase = (unsigned)__cvta_generic_to_shared(dyn);

    const int bm = blockIdx.y * GBM, bn = blockIdx.x * GBN;
    const int tid = threadIdx.x, lane = tid & 31, wid = tid >> 5;
    const int wm = (wid >> 2) * 64, wn = (wid & 3) * 32;
    const int g4 = lane >> 2, t4 = lane & 3;

    const int r8 = lane & 7, sel = lane >> 3;
    unsigned aoff[4], boff[2];
#pragma unroll
    for (int mf = 0; mf < 4; mf++)
        aoff[mf] = (unsigned)((wm + mf * 16 + r8 + ((sel & 1) << 3)) * (RST*2)
                              + ((sel >> 1) << 4));
#pragma unroll
    for (int p = 0; p < 2; p++)
        boff[p] = (unsigned)((wn + p * 16 + r8 + ((sel >> 1) << 3)) * (RST*2)
                              + ((sel & 1) << 4));

    float acc[4][4][4];
#pragma unroll
    for (int i = 0; i < 4; i++)
#pragma unroll
        for (int j = 0; j < 4; j++)
#pragma unroll
            for (int r = 0; r < 4; r++) acc[i][j][r] = 0.f;

    const int nk = K / GBK;

#define LOADSTAGE(s, k0) {                                                        \
        unsigned sb = sbase + (s) * STGB;                                         \
        _Pragma("unroll")                                                         \
        for (int rr = 0; rr < 2; rr++) {                                          \
            int idx = tid + rr * 256;                                             \
            int row = idx >> 2, cb = (idx & 3) * 8;                               \
            unsigned so = (unsigned)(row * (RST*2) + cb * 2);                     \
            size_t ga = (size_t)(bm + row) * K + (k0) + cb;                       \
            size_t gb = (size_t)(bn + row) * K + (k0) + cb;                       \
            cp16s(sb            + so, Ah + ga);                                   \
            cp16s(sb +   BUFB   + so, Al + ga);                                   \
            cp16s(sb + 2*BUFB   + so, Bh + gb);                                   \
            cp16s(sb + 3*BUFB   + so, Bl + gb);                                   \
        }                                                                         \
    }

    LOADSTAGE(0, 0);
    CP_COMMIT;

    for (int kt = 0; kt < nk; kt++) {
        const int s = kt & 1;
        if (kt + 1 < nk) LOADSTAGE(s ^ 1, (kt + 1) * GBK);
        CP_COMMIT;
        CP_WAIT1;
        __syncthreads();

        const unsigned abase = sbase + s * STGB;
#pragma unroll
        for (int ks = 0; ks < 2; ks++) {
            const unsigned kb = (unsigned)(ks * 32);
            unsigned ah[4][4], al[4][4], bh[4][2], bl[4][2];
#pragma unroll
            for (int mf = 0; mf < 4; mf++) {
                unsigned ad = abase + aoff[mf] + kb;
                ldm_x4(ah[mf][0], ah[mf][1], ah[mf][2], ah[mf][3], ad);
                ldm_x4(al[mf][0], al[mf][1], al[mf][2], al[mf][3], ad + BUFB);
            }
#pragma unroll
            for (int p = 0; p < 2; p++) {
                unsigned bd = abase + 2*BUFB + boff[p] + kb;
                ldm_x4(bh[2*p][0], bh[2*p][1], bh[2*p+1][0], bh[2*p+1][1], bd);
                ldm_x4(bl[2*p][0], bl[2*p][1], bl[2*p+1][0], bl[2*p+1][1], bd + BUFB);
            }
#pragma unroll
            for (int mf = 0; mf < 4; mf++)
#pragma unroll
                for (int nf = 0; nf < 4; nf++) {
                    mma16(acc[mf][nf], al[mf], bh[nf]);
                    mma16(acc[mf][nf], ah[mf], bl[nf]);
                    mma16(acc[mf][nf], ah[mf], bh[nf]);
                }
        }
        __syncthreads();
    }

#pragma unroll
    for (int mf = 0; mf < 4; mf++) {
#pragma unroll
        for (int nf = 0; nf < 4; nf++) {
            int row = bm + wm + mf * 16 + g4;
            int col = bn + wn + nf * 8 + 2 * t4;
            float2 v0 = make_float2(acc[mf][nf][0], acc[mf][nf][1]);
            float2 v1 = make_float2(acc[mf][nf][2], acc[mf][nf][3]);
            *(float2*)(C + (size_t)row * N + col)       = v0;
            *(float2*)(C + (size_t)(row + 8) * N + col) = v1;
        }
    }
#undef LOADSTAGE
}

// ==================== transpose a_w/b_w into wT[2048][32] ====================
__global__ __launch_bounds__(256) void transpose_ab(
    const float* __restrict__ aw, const float* __restrict__ bw,
    float* __restrict__ wt)
{
    int idx = blockIdx.x * 256 + threadIdx.x;   // 65536 total
    int k2 = idx >> 5, j = idx & 31;
    float v = (j < 16) ? aw[(size_t)j * Cn + k2] : bw[(size_t)(j - 16) * Cn + k2];
    wt[(size_t)k2 * 32 + j] = v;
}

// ==================== beta / decay projections (weight-staged) ====================
#define PTM 16
__global__ __launch_bounds__(256) void proj_gb2(
    const float* __restrict__ x, const float* __restrict__ wt,
    const float* __restrict__ bbias, const float* __restrict__ betab,
    const float* __restrict__ alog, const float* __restrict__ dtb,
    float* __restrict__ decout, float* __restrict__ betaout)
{
    __shared__ float ws[256 * 32];
    __shared__ float xs[PTM][256];
    __shared__ float rawm[PTM][32];

    const int tid = threadIdx.x, lane = tid & 31, wid = tid >> 5;
    const int m0 = blockIdx.x * PTM;

    float acc0 = 0.f, acc1 = 0.f;

    for (int kc = 0; kc < Cn / 256; kc++) {
#pragma unroll
        for (int i = 0; i < 32; i++)
            ws[tid + i * 256] = wt[(size_t)kc * 256 * 32 + tid + i * 256];
#pragma unroll
        for (int i = 0; i < 16; i++) {
            int idx = tid + i * 256;
            int tk = idx >> 8, kk = idx & 255;
            xs[tk][kk] = x[(size_t)(m0 + tk) * Cn + kc * 256 + kk];
        }
        __syncthreads();

        const float* w0 = ws + lane;
#pragma unroll 4
        for (int k2 = 0; k2 < 256; k2++) {
            float wv = w0[k2 * 32];
            acc0 = fmaf(xs[2 * wid][k2], wv, acc0);
            acc1 = fmaf(xs[2 * wid + 1][k2], wv, acc1);
        }
        __syncthreads();
    }

    rawm[2 * wid][lane] = acc0;
    rawm[2 * wid + 1][lane] = acc1;
    __syncthreads();

    {
        int token = tid >> 4, hh = tid & 15;
        float sa = rawm[token][hh] + dtb[hh];
        float sp = (sa > 20.f) ? sa : log1pf(expf(sa));
        float g  = -expf(alog[hh]) * sp;
        size_t m = (size_t)(m0 + token);
        decout[m * Hn + hh] = expf(g);
        float sb = rawm[token][16 + hh] + bbias[hh] + betab[hh];
        betaout[m * Hn + hh] = 2.f / (1.f + expf(-sb));
    }
}

// ==================== fused causal conv(4) + silu + l2norm (q/k) ====================
__global__ __launch_bounds__(256) void conv_l2(
    const float* __restrict__ in, int off,
    const float* __restrict__ w, float* __restrict__ out, float scale)
{
    int unit = blockIdx.x * 8 + (threadIdx.x >> 5);   // m*16 + h
    int lane = threadIdx.x & 31;
    int m = unit >> 4, h = unit & 15;
    int t = m & (Tn - 1);
    int ch0 = h * 64;

    float y[2];
#pragma unroll
    for (int half = 0; half < 2; half++) {
        int c = lane + half * 32;
        const float* w4 = w + (size_t)(ch0 + c) * 4;
        const float* p = in + (size_t)m * 2048 + off + ch0 + c;
        float accv = 0.f;
#pragma unroll
        for (int j = 0; j < 4; j++) {
            int tt = t + j - 3;
            if (tt >= 0) accv = fmaf(w4[j], p[(ptrdiff_t)(j - 3) * 2048], accv);
        }
        y[half] = accv / (1.f + expf(-accv));
    }
    float ss = y[0] * y[0] + y[1] * y[1];
#pragma unroll
    for (int o = 16; o; o >>= 1) ss += __shfl_xor_sync(0xffffffffu, ss, o);
    float r = rsqrtf(ss + 1e-6f) * scale;
    out[(size_t)m * KEYD + ch0 + lane]      = y[0] * r;
    out[(size_t)m * KEYD + ch0 + lane + 32] = y[1] * r;
}

// ==================== causal depthwise conv(4) + silu (v) ====================
__global__ void conv_silu(
    const float* __restrict__ in, int ldin, int off,
    const float* __restrict__ w, float* __restrict__ out,
    int CH, int total)
{
    int idx = blockIdx.x * blockDim.x + threadIdx.x;
    if (idx >= total) return;
    int c = idx % CH;
    int t = (idx / CH) % Tn;
    int b = idx / (CH * Tn);
    const float* w4 = w + (size_t)c * 4;
    size_t base = ((size_t)b * Tn) * ldin + off + c;
    float accv = 0.f;
#pragma unroll
    for (int j = 0; j < 4; j++) {
        int tt = t + j - 3;
        if (tt >= 0) accv += w4[j] * in[base + (size_t)tt * ldin];
    }
    out[idx] = accv / (1.f + expf(-accv));
}

// ==================== gated delta rule recurrent scan ====================
// SPLIT=2, 128 threads (PROVEN). Inner math in packed f32x2 (halved FMA instrs).
// Thread (jl = tid>>1, kh = tid&1) owns S[k = kh*32 .. kh*32+31][col jl],
// stored as 16 packed f32x2.
#define SPLIT 2
#define CHK 16
__global__ __launch_bounds__(128) void scan_kernel(
    const float* __restrict__ qn, const float* __restrict__ kn,
    const float* __restrict__ vv, const float* __restrict__ dec,
    const float* __restrict__ bet, float* __restrict__ op)
{
    __shared__ __align__(16) float qs[2][CHK][64];
    __shared__ __align__(16) float ks[2][CHK][64];
    __shared__ __align__(16) float vs[2][CHK][64];
    __shared__ float gs[2][CHK], bs[2][CHK];

    const int bid = blockIdx.x;
    const int vh = bid & (SPLIT - 1);
    const int h  = (bid / SPLIT) & (Hn - 1);
    const int b  = bid / (SPLIT * Hn);
    const int tid = threadIdx.x;
    const int jl = tid >> 1, kh = tid & 1;

    u64t S2[16];
#pragma unroll
    for (int i = 0; i < 16; i++) S2[i] = 0ull;

#define LOADCHUNK(s, t0) {                                                          \
        _Pragma("unroll")                                                           \
        for (int rr = 0; rr < 2; rr++) {                                            \
            int idx = tid + rr * 128;                                               \
            int row = idx >> 4, q4i = (idx & 15) * 4;                               \
            size_t tb = (size_t)(b * Tn + (t0) + row);                              \
            cp16(&qs[s][row][q4i], qn + (tb * Hn + h) * 64 + q4i);                  \
            cp16(&ks[s][row][q4i], kn + (tb * Hn + h) * 64 + q4i);                  \
            cp16(&vs[s][row][q4i], vv + tb * VALD + h * DVn + vh * 64 + q4i);       \
        }                                                                           \
        if (tid < CHK)            cp4(&gs[s][tid],      dec + (size_t)(b*Tn+(t0)+tid)*Hn + h);        \
        else if (tid < 2*CHK)     cp4(&bs[s][tid-CHK],  bet + (size_t)(b*Tn+(t0)+tid-CHK)*Hn + h);    \
    }

    LOADCHUNK(0, 0);
    CP_COMMIT;

    const int NC = Tn / CHK;
    for (int c = 0; c < NC; c++) {
        const int s = c & 1;
        if (c + 1 < NC) LOADCHUNK(s ^ 1, (c + 1) * CHK);
        CP_COMMIT;
        CP_WAIT1;
        __syncthreads();

        const int t0 = c * CHK;
#pragma unroll 1
        for (int r = 0; r < CHK; r++) {
            const float ge  = gs[s][r];
            const float btc = bs[s][r];
            const float vj  = vs[s][r][jl];
            const u64t ge2 = pack2(ge, ge);
            const u64t* kp2 = (const u64t*)&ks[s][r][kh * 32];
            const u64t* qp2 = (const u64t*)&qs[s][r][kh * 32];

            u64t kreg2[16];
            u64t macc[4] = {0ull, 0ull, 0ull, 0ull};
#pragma unroll
            for (int i = 0; i < 16; i++) {
                u64t k2v = kp2[i];
                u64t s2  = mul2(S2[i], ge2);
                macc[i & 3] = fma2(k2v, s2, macc[i & 3]);
                S2[i] = s2;
                kreg2[i] = k2v;
            }
            float mem;
            {
                float a0, a1, b0, b1, c0, c1, d0, d1;
                unpack2(macc[0], a0, a1); unpack2(macc[1], b0, b1);
                unpack2(macc[2], c0, c1); unpack2(macc[3], d0, d1);
                mem = ((a0 + a1) + (b0 + b1)) + ((c0 + c1) + (d0 + d1));
            }
            mem += __shfl_xor_sync(0xffffffffu, mem, 1);
            const float delta = (vj - mem) * btc;
            const u64t d2 = pack2(delta, delta);

            u64t oacc[4] = {0ull, 0ull, 0ull, 0ull};
#pragma unroll
            for (int i = 0; i < 16; i++) {
                u64t s2 = fma2(kreg2[i], d2, S2[i]);
                oacc[i & 3] = fma2(qp2[i], s2, oacc[i & 3]);
                S2[i] = s2;
            }
            float ov;
            {
                float a0, a1, b0, b1, c0, c1, d0, d1;
                unpack2(oacc[0], a0, a1); unpack2(oacc[1], b0, b1);
                unpack2(oacc[2], c0, c1); unpack2(oacc[3], d0, d1);
                ov = ((a0 + a1) + (b0 + b1)) + ((c0 + c1) + (d0 + d1));
            }
            ov += __shfl_xor_sync(0xffffffffu, ov, 1);
            if (kh == 0)
                op[(((size_t)(b * Tn + t0 + r)) * Hn + h) * DVn + vh * 64 + jl] = ov;
        }
        __syncthreads();
    }
#undef LOADCHUNK
}

// ==================== RMS + silu gate, fused bf16 hi/lo split output ====================
__global__ __launch_bounds__(256) void rms_gate_split(
    const float* __restrict__ op, const float* __restrict__ vg,
    __nv_bfloat16* __restrict__ obh, __nv_bfloat16* __restrict__ obl)
{
    int grp = blockIdx.x * 8 + (threadIdx.x >> 5);   // grp = m*16 + h
    int lane = threadIdx.x & 31;
    const float4* src = (const float4*)(op + (size_t)grp * 128);
    float4 o4 = src[lane];
    float ss = o4.x * o4.x + o4.y * o4.y + o4.z * o4.z + o4.w * o4.w;
#pragma unroll
    for (int o = 16; o; o >>= 1) ss += __shfl_xor_sync(0xffffffffu, ss, o);
    float r = rsqrtf(ss * (1.f / 128.f) + 1.1920929e-7f);
    int m = grp >> 4, h = grp & 15;
    const float4* gp = (const float4*)(vg + (size_t)m * 4096 + 2048 + h * 128);
    float4 gg = gp[lane];
    float res[4];
    res[0] = o4.x * r * (gg.x / (1.f + expf(-gg.x)));
    res[1] = o4.y * r * (gg.y / (1.f + expf(-gg.y)));
    res[2] = o4.z * r * (gg.z / (1.f + expf(-gg.z)));
    res[3] = o4.w * r * (gg.w / (1.f + expf(-gg.w)));
    __nv_bfloat16 hv[4], lv[4];
#pragma unroll
    for (int i = 0; i < 4; i++) {
        hv[i] = __float2bfloat16(res[i]);
        lv[i] = __float2bfloat16(res[i] - __bfloat162float(hv[i]));
    }
    size_t off = (size_t)m * 2048 + h * 128 + lane * 4;
    *(uint2*)(obh + off) = *(uint2*)hv;
    *(uint2*)(obl + off) = *(uint2*)lv;
}

// ==================== launch ====================
extern "C" void kernel_launch(void* const* d_in, const int* in_sizes, int n_in,
                              void* d_out, int out_size)
{
    const float* x      = (const float*)d_in[0];
    const float* qk_w   = (const float*)d_in[1];
    const float* vg_w   = (const float*)d_in[2];
    const float* o_w    = (const float*)d_in[3];
    const float* a_w    = (const float*)d_in[4];
    const float* b_w    = (const float*)d_in[5];
    const float* b_bias = (const float*)d_in[6];
    const float* beta_b = (const float*)d_in[7];
    const float* A_log  = (const float*)d_in[8];
    const float* dt_b   = (const float*)d_in[9];
    const float* q_cw   = (const float*)d_in[10];
    const float* k_cw   = (const float*)d_in[11];
    const float* v_cw   = (const float*)d_in[12];
    float* out = (float*)d_out;

    float *qk, *vg, *q, *k, *v, *dc, *bt, *op, *wt;
    __nv_bfloat16 *xh, *xl, *qwh, *qwl, *vwh, *vwl, *owh, *owl, *obh, *obl;
    cudaGetSymbolAddress((void**)&qk, g_qk);
    cudaGetSymbolAddress((void**)&vg, g_vg);
    cudaGetSymbolAddress((void**)&q,  g_q);
    cudaGetSymbolAddress((void**)&k,  g_k);
    cudaGetSymbolAddress((void**)&v,  g_v);
    cudaGetSymbolAddress((void**)&dc, g_dc);
    cudaGetSymbolAddress((void**)&bt, g_bt);
    cudaGetSymbolAddress((void**)&op, g_op);
    cudaGetSymbolAddress((void**)&wt, g_wt);
    cudaGetSymbolAddress((void**)&xh, g_xh);   cudaGetSymbolAddress((void**)&xl, g_xl);
    cudaGetSymbolAddress((void**)&qwh, g_qwh); cudaGetSymbolAddress((void**)&qwl, g_qwl);
    cudaGetSymbolAddress((void**)&vwh, g_vwh); cudaGetSymbolAddress((void**)&vwl, g_vwl);
    cudaGetSymbolAddress((void**)&owh, g_owh); cudaGetSymbolAddress((void**)&owl, g_owl);
    cudaGetSymbolAddress((void**)&obh, g_obh); cudaGetSymbolAddress((void**)&obl, g_obl);

    cudaFuncSetAttribute(gemm_bf16x3, cudaFuncAttributeMaxDynamicSharedMemorySize, GEMM_SMEM);

    // 0) bf16 hi/lo splits + weight transpose
    split_bf16<<<(Mtok*Cn/4 + 255)/256, 256>>>(x, xh, xl, Mtok*Cn/4);
    split_bf16<<<(2048*Cn/4 + 255)/256, 256>>>(qk_w, qwh, qwl, 2048*Cn/4);
    split_bf16<<<(4096*Cn/4 + 255)/256, 256>>>(vg_w, vwh, vwl, 4096*Cn/4);
    split_bf16<<<(2048*Cn/4 + 255)/256, 256>>>(o_w,  owh, owl, 2048*Cn/4);
    transpose_ab<<<Cn*32/256, 256>>>(a_w, b_w, wt);

    // 1) big projections (separate launches, 2-stage pipeline — proven)
    gemm_bf16x3<<<dim3(2048/GBN, Mtok/GBM), 256, GEMM_SMEM>>>(xh, xl, qwh, qwl, qk, Mtok, 2048, Cn);
    gemm_bf16x3<<<dim3(4096/GBN, Mtok/GBM), 256, GEMM_SMEM>>>(xh, xl, vwh, vwl, vg, Mtok, 4096, Cn);

    // 2) beta + decay (weight-staged)
    proj_gb2<<<Mtok/PTM, 256>>>(x, wt, b_bias, beta_b, A_log, dt_b, dc, bt);

    // 3) fused conv+silu+l2norm for q,k; conv+silu for v
    conv_l2<<<Mtok * Hn / 8, 256>>>(qk, 0,    q_cw, q, 0.125f);
    conv_l2<<<Mtok * Hn / 8, 256>>>(qk, 1024, k_cw, k, 1.0f);
    {
        int tv = Mtok * VALD;
        conv_silu<<<(tv + 255) / 256, 256>>>(vg, 4096, 0, v_cw, v, VALD, tv);
    }

    // 4) recurrent scan (SPLIT=2, 128 threads, f32x2-packed math)
    scan_kernel<<<Bsz * Hn * SPLIT, 128>>>(q, k, v, dc, bt, op);

    // 5) RMS + gate + fused bf16 split
    rms_gate_split<<<Mtok * Hn / 8, 256>>>(op, vg, obh, obl);

    // 6) output projection
    gemm_bf16x3<<<dim3(2048/GBN, Mtok/GBM), 256, GEMM_SMEM>>>(obh, obl, owh, owl, out, Mtok, 2048, Cn);
}

// round 13
// speedup vs baseline: 1.2350x; 1.0128x over previous
#include <cuda_runtime.h>
#include <cuda_bf16.h>
#include <math.h>
#include <stdint.h>

// Problem constants
#define Bsz 4
#define Tn 2048
#define Cn 2048
#define Hn 16
#define DKn 64
#define DVn 128
#define Mtok (Bsz*Tn)          // 8192
#define KEYD (Hn*DKn)          // 1024
#define VALD (Hn*DVn)          // 2048

// -------------------- scratch (device globals, no allocation) --------------------
__device__ float g_qk[(size_t)Mtok*2048];   // x @ qk_w^T
__device__ float g_vg[(size_t)Mtok*4096];   // x @ vg_w^T
__device__ float g_q [(size_t)Mtok*KEYD];
__device__ float g_k [(size_t)Mtok*KEYD];
__device__ float g_v [(size_t)Mtok*VALD];
__device__ float g_dc[(size_t)Mtok*Hn];
__device__ float g_bt[(size_t)Mtok*Hn];
__device__ float g_op[(size_t)Mtok*VALD];
__device__ float g_wt[(size_t)Cn*32];       // transposed [a_w;b_w]

// bf16 hi/lo split operands for the tensor GEMMs
__device__ __nv_bfloat16 g_xh [(size_t)Mtok*Cn],  g_xl [(size_t)Mtok*Cn];
__device__ __nv_bfloat16 g_qwh[(size_t)2048*Cn],  g_qwl[(size_t)2048*Cn];
__device__ __nv_bfloat16 g_vwh[(size_t)4096*Cn],  g_vwl[(size_t)4096*Cn];
__device__ __nv_bfloat16 g_owh[(size_t)2048*Cn],  g_owl[(size_t)2048*Cn];
__device__ __nv_bfloat16 g_obh[(size_t)Mtok*VALD], g_obl[(size_t)Mtok*VALD];

// -------------------- cp.async helpers --------------------
__device__ __forceinline__ void cp16(void* s, const void* g) {
    unsigned ss = (unsigned)__cvta_generic_to_shared(s);
    asm volatile("cp.async.cg.shared.global [%0], [%1], 16;\n" :: "r"(ss), "l"(g));
}
__device__ __forceinline__ void cp16s(unsigned saddr, const void* g) {
    asm volatile("cp.async.cg.shared.global [%0], [%1], 16;\n" :: "r"(saddr), "l"(g));
}
__device__ __forceinline__ void cp4(void* s, const void* g) {
    unsigned ss = (unsigned)__cvta_generic_to_shared(s);
    asm volatile("cp.async.ca.shared.global [%0], [%1], 4;\n" :: "r"(ss), "l"(g));
}
#define CP_COMMIT asm volatile("cp.async.commit_group;\n" ::: "memory")
#define CP_WAIT1  asm volatile("cp.async.wait_group 1;\n" ::: "memory")
#define CP_WAIT0  asm volatile("cp.async.wait_group 0;\n" ::: "memory")

// bf16 mma m16n8k16
__device__ __forceinline__ void mma16(float* c, const unsigned* a, const unsigned* b) {
    asm volatile(
        "mma.sync.aligned.m16n8k16.row.col.f32.bf16.bf16.f32 "
        "{%0,%1,%2,%3},{%4,%5,%6,%7},{%8,%9},{%0,%1,%2,%3};\n"
        : "+f"(c[0]), "+f"(c[1]), "+f"(c[2]), "+f"(c[3])
        : "r"(a[0]), "r"(a[1]), "r"(a[2]), "r"(a[3]), "r"(b[0]), "r"(b[1]));
}

__device__ __forceinline__ void ldm_x4(unsigned& r0, unsigned& r1,
                                       unsigned& r2, unsigned& r3, unsigned addr) {
    asm volatile("ldmatrix.sync.aligned.m8n8.x4.shared.b16 {%0,%1,%2,%3}, [%4];"
                 : "=r"(r0), "=r"(r1), "=r"(r2), "=r"(r3) : "r"(addr));
}

// streaming store (evict-first) for float2
__device__ __forceinline__ void stcs2(float* p, float a, float b) {
    float2 v = make_float2(a, b);
    asm volatile("st.global.cs.v2.f32 [%0], {%1, %2};" :: "l"(p), "f"(v.x), "f"(v.y) : "memory");
}

// ==================== bf16 hi/lo split (generic) ====================
__device__ __forceinline__ void do_split4(const float* in, __nv_bfloat16* h,
                                          __nv_bfloat16* l, int i) {
    float4 v = ((const float4*)in)[i];
    __nv_bfloat162 h0, h1, l0, l1;
    h0.x = __float2bfloat16(v.x); l0.x = __float2bfloat16(v.x - __bfloat162float(h0.x));
    h0.y = __float2bfloat16(v.y); l0.y = __float2bfloat16(v.y - __bfloat162float(h0.y));
    h1.x = __float2bfloat16(v.z); l1.x = __float2bfloat16(v.z - __bfloat162float(h1.x));
    h1.y = __float2bfloat16(v.w); l1.y = __float2bfloat16(v.w - __bfloat162float(h1.y));
    ((__nv_bfloat162*)h)[2*i]   = h0; ((__nv_bfloat162*)h)[2*i+1] = h1;
    ((__nv_bfloat162*)l)[2*i]   = l0; ((__nv_bfloat162*)l)[2*i+1] = l1;
}

__global__ __launch_bounds__(256) void split_bf16(
    const float* __restrict__ in, __nv_bfloat16* __restrict__ h,
    __nv_bfloat16* __restrict__ l, int n4)
{
    int i = blockIdx.x * blockDim.x + threadIdx.x;
    if (i >= n4) return;
    do_split4(in, h, l, i);
}

// fused weight splits: qk_w (1M float4) | vg_w (2M) | o_w (1M)
#define QW4 (2048*Cn/4)
#define VW4 (4096*Cn/4)
#define OW4 (2048*Cn/4)
__global__ __launch_bounds__(256) void split_weights(
    const float* __restrict__ qkw, __nv_bfloat16* __restrict__ qwh, __nv_bfloat16* __restrict__ qwl,
    const float* __restrict__ vgw, __nv_bfloat16* __restrict__ vwh, __nv_bfloat16* __restrict__ vwl,
    const float* __restrict__ ow,  __nv_bfloat16* __restrict__ owh, __nv_bfloat16* __restrict__ owl)
{
    int i = blockIdx.x * blockDim.x + threadIdx.x;
    if (i < QW4) {
        do_split4(qkw, qwh, qwl, i);
    } else if (i < QW4 + VW4) {
        do_split4(vgw, vwh, vwl, i - QW4);
    } else if (i < QW4 + VW4 + OW4) {
        do_split4(ow, owh, owl, i - QW4 - VW4);
    }
}

// ==================== bf16x3 GEMM with ldmatrix: C[M,N] = A @ B^T ====================
// LOCKED: GBK=32, RST=40, 2-stage cp.async pipeline. Epilogue uses .cs stores.
#define GBM 128
#define GBN 128
#define GBK 32
#define RST 40
#define BUFB (128*RST*2)               // 10240 B per operand buffer
#define STGB (4*BUFB)                  // 40960 B per stage
#define GEMM_SMEM (2*STGB)             // 81920 B

__global__ __launch_bounds__(256) void gemm_bf16x3(
    const __nv_bfloat16* __restrict__ Ah, const __nv_bfloat16* __restrict__ Al,
    const __nv_bfloat16* __restrict__ Bh, const __nv_bfloat16* __restrict__ Bl,
    float* __restrict__ C, int M, int N, int K)
{
    extern __shared__ __align__(16) char dyn[];
    const unsigned sbase = (unsigned)__cvta_generic_to_shared(dyn);

    const int bm = blockIdx.y * GBM, bn = blockIdx.x * GBN;
    const int tid = threadIdx.x, lane = tid & 31, wid = tid >> 5;
    const int wm = (wid >> 2) * 64, wn = (wid & 3) * 32;
    const int g4 = lane >> 2, t4 = lane & 3;

    const int r8 = lane & 7, sel = lane >> 3;
    unsigned aoff[4], boff[2];
#pragma unroll
    for (int mf = 0; mf < 4; mf++)
        aoff[mf] = (unsigned)((wm + mf * 16 + r8 + ((sel & 1) << 3)) * (RST*2)
                              + ((sel >> 1) << 4));
#pragma unroll
    for (int p = 0; p < 2; p++)
        boff[p] = (unsigned)((wn + p * 16 + r8 + ((sel >> 1) << 3)) * (RST*2)
                              + ((sel & 1) << 4));

    float acc[4][4][4];
#pragma unroll
    for (int i = 0; i < 4; i++)
#pragma unroll
        for (int j = 0; j < 4; j++)
#pragma unroll
            for (int r = 0; r < 4; r++) acc[i][j][r] = 0.f;

    const int nk = K / GBK;

#define LOADSTAGE(s, k0) {                                                        \
        unsigned sb = sbase + (s) * STGB;                                         \
        _Pragma("unroll")                                                         \
        for (int rr = 0; rr < 2; rr++) {                                          \
            int idx = tid + rr * 256;                                             \
            int row = idx >> 2, cb = (idx & 3) * 8;                               \
            unsigned so = (unsigned)(row * (RST*2) + cb * 2);                     \
            size_t ga = (size_t)(bm + row) * K + (k0) + cb;                       \
            size_t gb = (size_t)(bn + row) * K + (k0) + cb;                       \
            cp16s(sb            + so, Ah + ga);                                   \
            cp16s(sb +   BUFB   + so, Al + ga);                                   \
            cp16s(sb + 2*BUFB   + so, Bh + gb);                                   \
            cp16s(sb + 3*BUFB   + so, Bl + gb);                                   \
        }                                                                         \
    }

    LOADSTAGE(0, 0);
    CP_COMMIT;

    for (int kt = 0; kt < nk; kt++) {
        const int s = kt & 1;
        if (kt + 1 < nk) LOADSTAGE(s ^ 1, (kt + 1) * GBK);
        CP_COMMIT;
        CP_WAIT1;
        __syncthreads();

        const unsigned abase = sbase + s * STGB;
#pragma unroll
        for (int ks = 0; ks < 2; ks++) {
            const unsigned kb = (unsigned)(ks * 32);
            unsigned ah[4][4], al[4][4], bh[4][2], bl[4][2];
#pragma unroll
            for (int mf = 0; mf < 4; mf++) {
                unsigned ad = abase + aoff[mf] + kb;
                ldm_x4(ah[mf][0], ah[mf][1], ah[mf][2], ah[mf][3], ad);
                ldm_x4(al[mf][0], al[mf][1], al[mf][2], al[mf][3], ad + BUFB);
            }
#pragma unroll
            for (int p = 0; p < 2; p++) {
                unsigned bd = abase + 2*BUFB + boff[p] + kb;
                ldm_x4(bh[2*p][0], bh[2*p][1], bh[2*p+1][0], bh[2*p+1][1], bd);
                ldm_x4(bl[2*p][0], bl[2*p][1], bl[2*p+1][0], bl[2*p+1][1], bd + BUFB);
            }
#pragma unroll
            for (int mf = 0; mf < 4; mf++)
#pragma unroll
                for (int nf = 0; nf < 4; nf++) {
                    mma16(acc[mf][nf], al[mf], bh[nf]);
                    mma16(acc[mf][nf], ah[mf], bl[nf]);
                    mma16(acc[mf][nf], ah[mf], bh[nf]);
                }
        }
        __syncthreads();
    }

    // epilogue with streaming stores (C never re-read soon; keep L2 for operands)
#pragma unroll
    for (int mf = 0; mf < 4; mf++) {
#pragma unroll
        for (int nf = 0; nf < 4; nf++) {
            int row = bm + wm + mf * 16 + g4;
            int col = bn + wn + nf * 8 + 2 * t4;
            stcs2(C + (size_t)row * N + col,       acc[mf][nf][0], acc[mf][nf][1]);
            stcs2(C + (size_t)(row + 8) * N + col, acc[mf][nf][2], acc[mf][nf][3]);
        }
    }
#undef LOADSTAGE
}

// ==================== transpose a_w/b_w into wT[2048][32] ====================
__global__ __launch_bounds__(256) void transpose_ab(
    const float* __restrict__ aw, const float* __restrict__ bw,
    float* __restrict__ wt)
{
    int idx = blockIdx.x * 256 + threadIdx.x;   // 65536 total
    int k2 = idx >> 5, j = idx & 31;
    float v = (j < 16) ? aw[(size_t)j * Cn + k2] : bw[(size_t)(j - 16) * Cn + k2];
    wt[(size_t)k2 * 32 + j] = v;
}

// ==================== beta / decay projections (weight-staged) ====================
#define PTM 16
__global__ __launch_bounds__(256) void proj_gb2(
    const float* __restrict__ x, const float* __restrict__ wt,
    const float* __restrict__ bbias, const float* __restrict__ betab,
    const float* __restrict__ alog, const float* __restrict__ dtb,
    float* __restrict__ decout, float* __restrict__ betaout)
{
    __shared__ float ws[256 * 32];
    __shared__ float xs[PTM][256];
    __shared__ float rawm[PTM][32];

    const int tid = threadIdx.x, lane = tid & 31, wid = tid >> 5;
    const int m0 = blockIdx.x * PTM;

    float acc0 = 0.f, acc1 = 0.f;

    for (int kc = 0; kc < Cn / 256; kc++) {
#pragma unroll
        for (int i = 0; i < 32; i++)
            ws[tid + i * 256] = wt[(size_t)kc * 256 * 32 + tid + i * 256];
#pragma unroll
        for (int i = 0; i < 16; i++) {
            int idx = tid + i * 256;
            int tk = idx >> 8, kk = idx & 255;
            xs[tk][kk] = x[(size_t)(m0 + tk) * Cn + kc * 256 + kk];
        }
        __syncthreads();

        const float* w0 = ws + lane;
#pragma unroll 4
        for (int k2 = 0; k2 < 256; k2++) {
            float wv = w0[k2 * 32];
            acc0 = fmaf(xs[2 * wid][k2], wv, acc0);
            acc1 = fmaf(xs[2 * wid + 1][k2], wv, acc1);
        }
        __syncthreads();
    }

    rawm[2 * wid][lane] = acc0;
    rawm[2 * wid + 1][lane] = acc1;
    __syncthreads();

    {
        int token = tid >> 4, hh = tid & 15;
        float sa = rawm[token][hh] + dtb[hh];
        float sp = (sa > 20.f) ? sa : log1pf(expf(sa));
        float g  = -expf(alog[hh]) * sp;
        size_t m = (size_t)(m0 + token);
        decout[m * Hn + hh] = expf(g);
        float sb = rawm[token][16 + hh] + bbias[hh] + betab[hh];
        betaout[m * Hn + hh] = 2.f / (1.f + expf(-sb));
    }
}

// ==================== fused causal conv(4) + silu + l2norm (q/k) ====================
__global__ __launch_bounds__(256) void conv_l2(
    const float* __restrict__ in, int off,
    const float* __restrict__ w, float* __restrict__ out, float scale)
{
    int unit = blockIdx.x * 8 + (threadIdx.x >> 5);   // m*16 + h
    int lane = threadIdx.x & 31;
    int m = unit >> 4, h = unit & 15;
    int t = m & (Tn - 1);
    int ch0 = h * 64;

    float y[2];
#pragma unroll
    for (int half = 0; half < 2; half++) {
        int c = lane + half * 32;
        const float* w4 = w + (size_t)(ch0 + c) * 4;
        const float* p = in + (size_t)m * 2048 + off + ch0 + c;
        float accv = 0.f;
#pragma unroll
        for (int j = 0; j < 4; j++) {
            int tt = t + j - 3;
            if (tt >= 0) accv = fmaf(w4[j], p[(ptrdiff_t)(j - 3) * 2048], accv);
        }
        y[half] = accv / (1.f + expf(-accv));
    }
    float ss = y[0] * y[0] + y[1] * y[1];
#pragma unroll
    for (int o = 16; o; o >>= 1) ss += __shfl_xor_sync(0xffffffffu, ss, o);
    float r = rsqrtf(ss + 1e-6f) * scale;
    out[(size_t)m * KEYD + ch0 + lane]      = y[0] * r;
    out[(size_t)m * KEYD + ch0 + lane + 32] = y[1] * r;
}

// ==================== causal depthwise conv(4) + silu (v) ====================
__global__ void conv_silu(
    const float* __restrict__ in, int ldin, int off,
    const float* __restrict__ w, float* __restrict__ out,
    int CH, int total)
{
    int idx = blockIdx.x * blockDim.x + threadIdx.x;
    if (idx >= total) return;
    int c = idx % CH;
    int t = (idx / CH) % Tn;
    int b = idx / (CH * Tn);
    const float* w4 = w + (size_t)c * 4;
    size_t base = ((size_t)b * Tn) * ldin + off + c;
    float accv = 0.f;
#pragma unroll
    for (int j = 0; j < 4; j++) {
        int tt = t + j - 3;
        if (tt >= 0) accv += w4[j] * in[base + (size_t)tt * ldin];
    }
    out[idx] = accv / (1.f + expf(-accv));
}

// ==================== gated delta rule recurrent scan (R8-proven scalar) ====================
#define SPLIT 2
#define CHK 16
__global__ __launch_bounds__(128) void scan_kernel(
    const float* __restrict__ qn, const float* __restrict__ kn,
    const float* __restrict__ vv, const float* __restrict__ dec,
    const float* __restrict__ bet, float* __restrict__ op)
{
    __shared__ __align__(16) float qs[2][CHK][64];
    __shared__ __align__(16) float ks[2][CHK][64];
    __shared__ __align__(16) float vs[2][CHK][64];
    __shared__ float gs[2][CHK], bs[2][CHK];

    const int bid = blockIdx.x;
    const int vh = bid & (SPLIT - 1);
    const int h  = (bid / SPLIT) & (Hn - 1);
    const int b  = bid / (SPLIT * Hn);
    const int tid = threadIdx.x;
    const int jl = tid >> 1, kh = tid & 1;

    float S[32];
#pragma unroll
    for (int i = 0; i < 32; i++) S[i] = 0.f;

#define LOADCHUNK(s, t0) {                                                          \
        _Pragma("unroll")                                                           \
        for (int rr = 0; rr < 2; rr++) {                                            \
            int idx = tid + rr * 128;                                               \
            int row = idx >> 4, q4i = (idx & 15) * 4;                               \
            size_t tb = (size_t)(b * Tn + (t0) + row);                              \
            cp16(&qs[s][row][q4i], qn + (tb * Hn + h) * 64 + q4i);                  \
            cp16(&ks[s][row][q4i], kn + (tb * Hn + h) * 64 + q4i);                  \
            cp16(&vs[s][row][q4i], vv + tb * VALD + h * DVn + vh * 64 + q4i);       \
        }                                                                           \
        if (tid < CHK)            cp4(&gs[s][tid],      dec + (size_t)(b*Tn+(t0)+tid)*Hn + h);        \
        else if (tid < 2*CHK)     cp4(&bs[s][tid-CHK],  bet + (size_t)(b*Tn+(t0)+tid-CHK)*Hn + h);    \
    }

    LOADCHUNK(0, 0);
    CP_COMMIT;

    const int NC = Tn / CHK;
    for (int c = 0; c < NC; c++) {
        const int s = c & 1;
        if (c + 1 < NC) LOADCHUNK(s ^ 1, (c + 1) * CHK);
        CP_COMMIT;
        CP_WAIT1;
        __syncthreads();

        const int t0 = c * CHK;
#pragma unroll 1
        for (int r = 0; r < CHK; r++) {
            const float ge  = gs[s][r];
            const float btc = bs[s][r];
            const float vj  = vs[s][r][jl];
            const float4* kp = (const float4*)&ks[s][r][kh * 32];
            const float4* qp = (const float4*)&qs[s][r][kh * 32];

            float kreg[32];
            float m0 = 0.f, m1 = 0.f, m2 = 0.f, m3 = 0.f;
#pragma unroll
            for (int i = 0; i < 8; i++) {
                float4 k4 = kp[i];
                float s0 = S[4*i+0] * ge, s1 = S[4*i+1] * ge;
                float s2 = S[4*i+2] * ge, s3 = S[4*i+3] * ge;
                m0 += k4.x * s0; m1 += k4.y * s1; m2 += k4.z * s2; m3 += k4.w * s3;
                S[4*i+0] = s0; S[4*i+1] = s1; S[4*i+2] = s2; S[4*i+3] = s3;
                kreg[4*i+0] = k4.x; kreg[4*i+1] = k4.y;
                kreg[4*i+2] = k4.z; kreg[4*i+3] = k4.w;
            }
            float mem = (m0 + m1) + (m2 + m3);
            mem += __shfl_xor_sync(0xffffffffu, mem, 1);
            const float delta = (vj - mem) * btc;

            float o0 = 0.f, o1 = 0.f, o2 = 0.f, o3 = 0.f;
#pragma unroll
            for (int i = 0; i < 8; i++) {
                float4 q4 = qp[i];
                float s0 = S[4*i+0] + kreg[4*i+0] * delta;
                float s1 = S[4*i+1] + kreg[4*i+1] * delta;
                float s2 = S[4*i+2] + kreg[4*i+2] * delta;
                float s3 = S[4*i+3] + kreg[4*i+3] * delta;
                o0 += q4.x * s0; o1 += q4.y * s1; o2 += q4.z * s2; o3 += q4.w * s3;
                S[4*i+0] = s0; S[4*i+1] = s1; S[4*i+2] = s2; S[4*i+3] = s3;
            }
            float ov = (o0 + o1) + (o2 + o3);
            ov += __shfl_xor_sync(0xffffffffu, ov, 1);
            if (kh == 0)
                op[(((size_t)(b * Tn + t0 + r)) * Hn + h) * DVn + vh * 64 + jl] = ov;
        }
        __syncthreads();
    }
#undef LOADCHUNK
}

// ==================== RMS + silu gate, fused bf16 hi/lo split output ====================
__global__ __launch_bounds__(256) void rms_gate_split(
    const float* __restrict__ op, const float* __restrict__ vg,
    __nv_bfloat16* __restrict__ obh, __nv_bfloat16* __restrict__ obl)
{
    int grp = blockIdx.x * 8 + (threadIdx.x >> 5);   // grp = m*16 + h
    int lane = threadIdx.x & 31;
    const float4* src = (const float4*)(op + (size_t)grp * 128);
    float4 o4 = src[lane];
    float ss = o4.x * o4.x + o4.y * o4.y + o4.z * o4.z + o4.w * o4.w;
#pragma unroll
    for (int o = 16; o; o >>= 1) ss += __shfl_xor_sync(0xffffffffu, ss, o);
    float r = rsqrtf(ss * (1.f / 128.f) + 1.1920929e-7f);
    int m = grp >> 4, h = grp & 15;
    const float4* gp = (const float4*)(vg + (size_t)m * 4096 + 2048 + h * 128);
    float4 gg = gp[lane];
    float res[4];
    res[0] = o4.x * r * (gg.x / (1.f + expf(-gg.x)));
    res[1] = o4.y * r * (gg.y / (1.f + expf(-gg.y)));
    res[2] = o4.z * r * (gg.z / (1.f + expf(-gg.z)));
    res[3] = o4.w * r * (gg.w / (1.f + expf(-gg.w)));
    __nv_bfloat16 hv[4], lv[4];
#pragma unroll
    for (int i = 0; i < 4; i++) {
        hv[i] = __float2bfloat16(res[i]);
        lv[i] = __float2bfloat16(res[i] - __bfloat162float(hv[i]));
    }
    size_t off = (size_t)m * 2048 + h * 128 + lane * 4;
    *(uint2*)(obh + off) = *(uint2*)hv;
    *(uint2*)(obl + off) = *(uint2*)lv;
}

// ==================== launch ====================
extern "C" void kernel_launch(void* const* d_in, const int* in_sizes, int n_in,
                              void* d_out, int out_size)
{
    const float* x      = (const float*)d_in[0];
    const float* qk_w   = (const float*)d_in[1];
    const float* vg_w   = (const float*)d_in[2];
    const float* o_w    = (const float*)d_in[3];
    const float* a_w    = (const float*)d_in[4];
    const float* b_w    = (const float*)d_in[5];
    const float* b_bias = (const float*)d_in[6];
    const float* beta_b = (const float*)d_in[7];
    const float* A_log  = (const float*)d_in[8];
    const float* dt_b   = (const float*)d_in[9];
    const float* q_cw   = (const float*)d_in[10];
    const float* k_cw   = (const float*)d_in[11];
    const float* v_cw   = (const float*)d_in[12];
    float* out = (float*)d_out;

    float *qk, *vg, *q, *k, *v, *dc, *bt, *op, *wt;
    __nv_bfloat16 *xh, *xl, *qwh, *qwl, *vwh, *vwl, *owh, *owl, *obh, *obl;
    cudaGetSymbolAddress((void**)&qk, g_qk);
    cudaGetSymbolAddress((void**)&vg, g_vg);
    cudaGetSymbolAddress((void**)&q,  g_q);
    cudaGetSymbolAddress((void**)&k,  g_k);
    cudaGetSymbolAddress((void**)&v,  g_v);
    cudaGetSymbolAddress((void**)&dc, g_dc);
    cudaGetSymbolAddress((void**)&bt, g_bt);
    cudaGetSymbolAddress((void**)&op, g_op);
    cudaGetSymbolAddress((void**)&wt, g_wt);
    cudaGetSymbolAddress((void**)&xh, g_xh);   cudaGetSymbolAddress((void**)&xl, g_xl);
    cudaGetSymbolAddress((void**)&qwh, g_qwh); cudaGetSymbolAddress((void**)&qwl, g_qwl);
    cudaGetSymbolAddress((void**)&vwh, g_vwh); cudaGetSymbolAddress((void**)&vwl, g_vwl);
    cudaGetSymbolAddress((void**)&owh, g_owh); cudaGetSymbolAddress((void**)&owl, g_owl);
    cudaGetSymbolAddress((void**)&obh, g_obh); cudaGetSymbolAddress((void**)&obl, g_obl);

    cudaFuncSetAttribute(gemm_bf16x3, cudaFuncAttributeMaxDynamicSharedMemorySize, GEMM_SMEM);

    // 0) bf16 hi/lo splits (x separate; three weight splits fused) + weight transpose
    split_bf16<<<(Mtok*Cn/4 + 255)/256, 256>>>(x, xh, xl, Mtok*Cn/4);
    {
        int tw = QW4 + VW4 + OW4;
        split_weights<<<(tw + 255)/256, 256>>>(qk_w, qwh, qwl, vg_w, vwh, vwl, o_w, owh, owl);
    }
    transpose_ab<<<Cn*32/256, 256>>>(a_w, b_w, wt);

    // 1) big projections (separate launches, 2-stage pipeline — proven)
    gemm_bf16x3<<<dim3(2048/GBN, Mtok/GBM), 256, GEMM_SMEM>>>(xh, xl, qwh, qwl, qk, Mtok, 2048, Cn);
    gemm_bf16x3<<<dim3(4096/GBN, Mtok/GBM), 256, GEMM_SMEM>>>(xh, xl, vwh, vwl, vg, Mtok, 4096, Cn);

    // 2) beta + decay (weight-staged)
    proj_gb2<<<Mtok/PTM, 256>>>(x, wt, b_bias, beta_b, A_log, dt_b, dc, bt);

    // 3) fused conv+silu+l2norm for q,k; conv+silu for v
    conv_l2<<<Mtok * Hn / 8, 256>>>(qk, 0,    q_cw, q, 0.125f);
    conv_l2<<<Mtok * Hn / 8, 256>>>(qk, 1024, k_cw, k, 1.0f);
    {
        int tv = Mtok * VALD;
        conv_silu<<<(tv + 255) / 256, 256>>>(vg, 4096, 0, v_cw, v, VALD, tv);
    }

    // 4) recurrent scan (SPLIT=2, 128 threads, scalar — proven)
    scan_kernel<<<Bsz * Hn * SPLIT, 128>>>(q, k, v, dc, bt, op);

    // 5) RMS + gate + fused bf16 split
    rms_gate_split<<<Mtok * Hn / 8, 256>>>(op, vg, obh, obl);

    // 6) output projection
    gemm_bf16x3<<<dim3(2048/GBN, Mtok/GBM), 256, GEMM_SMEM>>>(obh, obl, owh, owl, out, Mtok, 2048, Cn);
}